// round 14
// baseline (speedup 1.0000x reference)
#include <cuda_runtime.h>
#include <cuda_fp16.h>
#include <stdint.h>

// ---------------- problem constants ----------------
#define BT    4096        // B*T
#define SEQT  2048        // T
#define DIM   1024        // D
#define T3D   3072        // 3*D
#define DIFF  2048        // DI
#define NL    8           // layers
#define NVOC  32000       // vocab

#define QKV_WN ((long long)NL * T3D * DIM)
#define O_WN   ((long long)NL * DIM * DIM)
#define G_WN   ((long long)NL * DIFF * DIM)
#define D_WN   ((long long)NL * DIM * DIFF)
#define E_WN   ((long long)NVOC * DIM)

// ---------------- scratch ----------------
__device__ float g_x[BT * DIM];               // residual (fp32)
__device__ float g_gate[BT * DIFF];           // gate pre-act (fp32)
__device__ __half g_q3h[BT * T3D], g_q3l[BT * T3D]; // qkv hi/lo (fp16)
__device__ __half g_hh[BT * DIM];             // activations hi (fp16)
__device__ __half g_2h[BT * DIFF];            // mlp mid hi (fp16)
// fp8 activation streams for correction passes
__device__ unsigned char g_a8[BT * DIM],  g_al8[BT * DIM];    // attn out, lo*512
__device__ unsigned char g_m8[BT * DIFF], g_ml8[BT * DIFF];   // mlp mid, lo*512
// weights: fp16 hi for all; fp8 (lo*2^13, hi*2^4) for o/down corrections
__device__ __half g_qkvh[QKV_WN];
__device__ __half g_owh[O_WN];
__device__ unsigned char g_owl8[O_WN], g_owh8[O_WN];
__device__ __half g_gwh[G_WN];
__device__ __half g_uwh[G_WN];
__device__ __half g_dwh[D_WN];
__device__ unsigned char g_dwl8[D_WN], g_dwh8[D_WN];
__device__ __half g_embh[E_WN];

// ---------------- helpers ----------------
__device__ __forceinline__ uint32_t smem_u32(const void* p) {
    uint32_t a;
    asm("{ .reg .u64 t; cvta.to.shared.u64 t, %1; cvt.u32.u64 %0, t; }" : "=r"(a) : "l"(p));
    return a;
}
__device__ __forceinline__ void ldm4(uint32_t* r, uint32_t a) {
    asm volatile("ldmatrix.sync.aligned.m8n8.x4.shared.b16 {%0,%1,%2,%3}, [%4];"
                 : "=r"(r[0]), "=r"(r[1]), "=r"(r[2]), "=r"(r[3]) : "r"(a));
}
__device__ __forceinline__ void ldm4t(uint32_t* r, uint32_t a) {
    asm volatile("ldmatrix.sync.aligned.m8n8.x4.trans.shared.b16 {%0,%1,%2,%3}, [%4];"
                 : "=r"(r[0]), "=r"(r[1]), "=r"(r[2]), "=r"(r[3]) : "r"(a));
}
__device__ __forceinline__ void mma16816(float* d, const uint32_t* a, const uint32_t* b) {
    asm volatile(
        "mma.sync.aligned.m16n8k16.row.col.f32.f16.f16.f32 "
        "{%0,%1,%2,%3}, {%4,%5,%6,%7}, {%8,%9}, {%0,%1,%2,%3};"
        : "+f"(d[0]), "+f"(d[1]), "+f"(d[2]), "+f"(d[3])
        : "r"(a[0]), "r"(a[1]), "r"(a[2]), "r"(a[3]), "r"(b[0]), "r"(b[1]));
}
// fp8 e4m3 MMA, k32 (base PTX since sm_89)
__device__ __forceinline__ void mma8(float* d, const uint32_t* a, const uint32_t* b) {
    asm volatile(
        "mma.sync.aligned.m16n8k32.row.col.f32.e4m3.e4m3.f32 "
        "{%0,%1,%2,%3}, {%4,%5,%6,%7}, {%8,%9}, {%0,%1,%2,%3};"
        : "+f"(d[0]), "+f"(d[1]), "+f"(d[2]), "+f"(d[3])
        : "r"(a[0]), "r"(a[1]), "r"(a[2]), "r"(a[3]), "r"(b[0]), "r"(b[1]));
}
__device__ __forceinline__ uint32_t lds32(uint32_t a) {
    uint32_t v;
    asm volatile("ld.shared.b32 %0, [%1];" : "=r"(v) : "r"(a));
    return v;
}
__device__ __forceinline__ void cpa16(uint32_t d, const void* s) {
    asm volatile("cp.async.cg.shared.global [%0], [%1], 16;" :: "r"(d), "l"(s));
}
__device__ __forceinline__ uint32_t pkh2(float x, float y) {
    __half2 h = __floats2half2_rn(x, y);
    return *reinterpret_cast<uint32_t*>(&h);
}
__device__ __forceinline__ void split2h(float x, float y, uint32_t& h, uint32_t& l) {
    __half2 hb = __floats2half2_rn(x, y);
    h = *reinterpret_cast<uint32_t*>(&hb);
    l = pkh2(x - __half2float(__low2half(hb)), y - __half2float(__high2half(hb)));
}
// pack two floats -> e4m3x2 (x -> byte0, y -> byte1)
__device__ __forceinline__ uint16_t pk8(float x, float y) {
    uint16_t r;
    asm("cvt.rn.satfinite.e4m3x2.f32 %0, %1, %2;" : "=h"(r) : "f"(y), "f"(x));
    return r;
}
__device__ __forceinline__ float silu_f(float x) { return x / (1.f + __expf(-x)); }

// ---------------- weight convert: fp32 -> fp16 (hi only) ----------------
__global__ void conv_kernel(const float* __restrict__ s,
                            __half* __restrict__ H, long long n)
{
    long long i = ((long long)blockIdx.x * 256 + threadIdx.x) * 4;
    if (i >= n) return;
    float4 v = *(const float4*)(s + i);
    *(uint2*)(H + i) = make_uint2(pkh2(v.x, v.y), pkh2(v.z, v.w));
}

// ---------------- weight split: fp32 -> fp16 hi + fp8 lo/hi ----------------
__global__ void wsplit8_kernel(const float* __restrict__ s,
                               __half* __restrict__ H,
                               unsigned char* __restrict__ L8,
                               unsigned char* __restrict__ H8, long long n)
{
    long long i = ((long long)blockIdx.x * 256 + threadIdx.x) * 4;
    if (i >= n) return;
    float4 v = *(const float4*)(s + i);
    __half2 ha = __floats2half2_rn(v.x, v.y);
    __half2 hb = __floats2half2_rn(v.z, v.w);
    *(uint2*)(H + i) = make_uint2(*reinterpret_cast<uint32_t*>(&ha),
                                  *reinterpret_cast<uint32_t*>(&hb));
    float l0 = v.x - __half2float(ha.x), l1 = v.y - __half2float(ha.y);
    float l2 = v.z - __half2float(hb.x), l3 = v.w - __half2float(hb.y);
    uint32_t wl = (uint32_t)pk8(l0 * 8192.f, l1 * 8192.f)
                | ((uint32_t)pk8(l2 * 8192.f, l3 * 8192.f) << 16);
    uint32_t wh = (uint32_t)pk8(v.x * 16.f, v.y * 16.f)
                | ((uint32_t)pk8(v.z * 16.f, v.w * 16.f) << 16);
    *(uint32_t*)(L8 + i) = wl;
    *(uint32_t*)(H8 + i) = wh;
}

// EPI 0: C=acc ; 1: C+=acc ; 2: OH=fp16(silu(C)*acc), O8/O8L=fp8 streams ;
// 3: OH/OL = fp16 hi/lo split(acc)
template <int EPI>
__device__ __forceinline__ void epi2(float* __restrict__ C,
                                     __half* __restrict__ OH,
                                     __half* __restrict__ OL,
                                     unsigned char* __restrict__ O8,
                                     unsigned char* __restrict__ O8L,
                                     long long off, float x, float y)
{
    if (EPI == 0) {
        *(float2*)(C + off) = make_float2(x, y);
    } else if (EPI == 1) {
        float2 c = *(const float2*)(C + off);
        *(float2*)(C + off) = make_float2(c.x + x, c.y + y);
    } else if (EPI == 2) {
        float2 c = *(const float2*)(C + off);
        x = silu_f(c.x) * x;
        y = silu_f(c.y) * y;
        __half2 hb = __floats2half2_rn(x, y);
        *(uint32_t*)(OH + off) = *reinterpret_cast<uint32_t*>(&hb);
        *(uint16_t*)(O8 + off) = pk8(x, y);
        float lx = x - __half2float(hb.x), ly = y - __half2float(hb.y);
        *(uint16_t*)(O8L + off) = pk8(lx * 512.f, ly * 512.f);
    } else {
        uint32_t h, l;
        split2h(x, y, h, l);
        *(uint32_t*)(OH + off) = h;
        *(uint32_t*)(OL + off) = l;
    }
}

// ============ single-pass fp16 mma.sync GEMM (R11 mainloop) ============
// C[M,N] (+)= A[M,K] @ W[N,K]^T, fp32 accumulate.
// CTA tile 64x128, BK=64, 256 threads = 8 warps (2 M x 4 N, warp 32x32).
// Stage 24KB (A 8KB @0, W 16KB @8K), 4 stages = 96KB -> 2 CTAs/SM.
#define GSS 24576u
template <int EPI>
__global__ void __launch_bounds__(256, 2) gemm_p(
    const __half* __restrict__ A0, const __half* __restrict__ W0,
    float* __restrict__ C, __half* __restrict__ OH, __half* __restrict__ OL,
    unsigned char* __restrict__ O8, unsigned char* __restrict__ O8L,
    int N, int K)
{
    extern __shared__ char dsm_raw[];
    char* dsm = (char*)(((uintptr_t)dsm_raw + 1023) & ~(uintptr_t)1023);
    const uint32_t sb = smem_u32(dsm);

    const int tid = threadIdx.x;
    const int wid = tid >> 5;
    const int lane = tid & 31;
    const int m0 = blockIdx.y * 64;
    const int n0 = blockIdx.x * 128;

    const int prow = tid >> 3;
    const int pcc  = tid & 7;
    const long long aoff = (long long)(m0 + prow) * K + pcc * 8;
    const long long woff = (long long)(n0 + prow) * K + pcc * 8;
    const uint32_t pdst = (uint32_t)prow * 128u +
                          (((uint32_t)pcc * 16u) ^ ((uint32_t)(prow & 7) << 4));
    const uint32_t dA = sb + pdst;
    const uint32_t dW = sb + 8192u + pdst;

    const int wm = (wid >> 2) * 32;
    const int wn = (wid & 3) * 32;
    const int lrow = ((lane >> 3) & 1) * 8 + (lane & 7);
    const uint32_t lcol = ((uint32_t)lane >> 4) * 16;
    uint32_t aOff[2], aXor[2], bOff[2], bXor[2];
#pragma unroll
    for (int t = 0; t < 2; t++) {
        int ra = wm + t * 16 + lrow;
        aOff[t] = (uint32_t)ra * 128u; aXor[t] = (uint32_t)(ra & 7) << 4;
        int rb = wn + t * 16 + lrow;
        bOff[t] = 8192u + (uint32_t)rb * 128u; bXor[t] = (uint32_t)(rb & 7) << 4;
    }

    float acc[2][4][4];
#pragma unroll
    for (int i = 0; i < 2; i++)
#pragma unroll
        for (int j = 0; j < 4; j++)
#pragma unroll
            for (int k = 0; k < 4; k++) acc[i][j][k] = 0.f;

    const int NT = K >> 6;

#pragma unroll
    for (int st = 0; st < 3; st++) {
        if (st < NT) {
            const uint32_t bo = (uint32_t)st * GSS;
            const int lk = st * 64;
            cpa16(dA + bo,          A0 + aoff + lk);
            cpa16(dA + bo + 4096u,  A0 + aoff + (long long)32 * K + lk);
#pragma unroll
            for (int i = 0; i < 4; i++)
                cpa16(dW + bo + 4096u * i, W0 + woff + (long long)32 * K * i + lk);
        }
        asm volatile("cp.async.commit_group;" ::: "memory");
    }

    for (int kt = 0; kt < NT; kt++) {
        asm volatile("cp.async.wait_group 2;" ::: "memory");
        __syncthreads();
        const uint32_t buf = sb + (uint32_t)(kt & 3) * GSS;

#pragma unroll
        for (int s = 0; s < 4; s++) {
            const uint32_t cb = (uint32_t)s * 32;
            uint32_t ah[2][4], bh[2][4];
#pragma unroll
            for (int t = 0; t < 2; t++) {
                ldm4(ah[t], buf + aOff[t] + ((cb + lcol) ^ aXor[t]));
                ldm4(bh[t], buf + bOff[t] + ((cb + lcol) ^ bXor[t]));
            }
#pragma unroll
            for (int mt = 0; mt < 2; mt++)
#pragma unroll
                for (int n8 = 0; n8 < 4; n8++) {
                    uint32_t bf[2] = { bh[n8 >> 1][n8 & 1], bh[n8 >> 1][(n8 & 1) + 2] };
                    mma16816(acc[mt][n8], ah[mt], bf);
                }
        }

        if (kt + 3 < NT) {
            const uint32_t bo = (uint32_t)((kt + 3) & 3) * GSS;
            const int lk = (kt + 3) * 64;
            cpa16(dA + bo,          A0 + aoff + lk);
            cpa16(dA + bo + 4096u,  A0 + aoff + (long long)32 * K + lk);
#pragma unroll
            for (int i = 0; i < 4; i++)
                cpa16(dW + bo + 4096u * i, W0 + woff + (long long)32 * K * i + lk);
        }
        asm volatile("cp.async.commit_group;" ::: "memory");
    }

    const int er = lane >> 2;
    const int ec = (lane & 3) * 2;
#pragma unroll
    for (int mt = 0; mt < 2; mt++) {
        const int row = m0 + wm + mt * 16 + er;
#pragma unroll
        for (int n8 = 0; n8 < 4; n8++) {
            const int col = n0 + wn + n8 * 8 + ec;
            long long off = (long long)row * N + col;
            epi2<EPI>(C, OH, OL, O8, O8L, off,                    acc[mt][n8][0], acc[mt][n8][1]);
            epi2<EPI>(C, OH, OL, O8, O8L, off + (long long)8 * N, acc[mt][n8][2], acc[mt][n8][3]);
        }
    }
}

// ============ fp8 correction GEMM: C += (A8*WL8 + AL8*WH8) * 2^-13 ============
// A8 = e4m3(A); AL8 = e4m3((A - fp16(A)) * 2^9); WL8 = e4m3((W - Wh) * 2^13);
// WH8 = e4m3(W * 2^4). Scales: 1*2^13 and 2^9*2^4 = 2^13 -> single merge scale.
// CTA tile 64x128, BK=64 fp8 elems, 256 threads = 8 warps (2 M x 4 N, warp 32x32).
// SMEM rows: 64 B data + 16 pad = 80 B stride (bank map (20g+t)%32: conflict-free).
// Stage: A8 5120 @0, AL8 @5120, WL8 10240 @10240, WH8 @20480 -> 30720; 3 stages.
#define CSS 30720u
__global__ void __launch_bounds__(256, 2) corr8(
    const unsigned char* __restrict__ A8g, const unsigned char* __restrict__ AL8g,
    const unsigned char* __restrict__ WL8g, const unsigned char* __restrict__ WH8g,
    float* __restrict__ C, int N, int K)
{
    extern __shared__ char dsm_raw[];
    char* dsm = (char*)(((uintptr_t)dsm_raw + 1023) & ~(uintptr_t)1023);
    const uint32_t sb = smem_u32(dsm);

    const int tid = threadIdx.x;
    const int wid = tid >> 5;
    const int lane = tid & 31;
    const int m0 = blockIdx.y * 64;
    const int n0 = blockIdx.x * 128;

    // producer: A/AL 64 rows x 4 chunks (1 each); W 128 rows x 4 (2 each)
    const int prow = tid >> 2;           // 0..63
    const int pc   = tid & 3;
    const long long aoff = (long long)(m0 + prow) * K + pc * 16;
    const uint32_t adst = (uint32_t)prow * 80u + (uint32_t)pc * 16u;
    long long woff[2]; uint32_t wdst[2];
#pragma unroll
    for (int i = 0; i < 2; i++) {
        int wr = prow + 64 * i;
        woff[i] = (long long)(n0 + wr) * K + pc * 16;
        wdst[i] = 10240u + (uint32_t)wr * 80u + (uint32_t)pc * 16u;
    }

    const int g  = lane >> 2;
    const int tg = lane & 3;
    const int wm = (wid >> 2) * 32;
    const int wn = (wid & 3) * 32;

    float acc[2][4][4];
#pragma unroll
    for (int i = 0; i < 2; i++)
#pragma unroll
        for (int j = 0; j < 4; j++)
#pragma unroll
            for (int k = 0; k < 4; k++) acc[i][j][k] = 0.f;

    const int NT = K >> 6;

#pragma unroll
    for (int st = 0; st < 2; st++) {
        if (st < NT) {
            const uint32_t bo = (uint32_t)st * CSS;
            const int lk = st * 64;
            cpa16(sb + bo + adst,          A8g  + aoff + lk);
            cpa16(sb + bo + adst + 5120u,  AL8g + aoff + lk);
#pragma unroll
            for (int i = 0; i < 2; i++) {
                cpa16(sb + bo + wdst[i],           WL8g + woff[i] + lk);
                cpa16(sb + bo + wdst[i] + 10240u,  WH8g + woff[i] + lk);
            }
        }
        asm volatile("cp.async.commit_group;" ::: "memory");
    }

    for (int kt = 0; kt < NT; kt++) {
        asm volatile("cp.async.wait_group 1;" ::: "memory");
        __syncthreads();
        const uint32_t buf = sb + (uint32_t)(kt % 3) * CSS;

#pragma unroll
        for (int s = 0; s < 2; s++) {            // two k32 steps per ktile
            const uint32_t kb = (uint32_t)s * 32u + 4u * (uint32_t)tg;
            uint32_t a8f[2][4], al8f[2][4];
#pragma unroll
            for (int mt = 0; mt < 2; mt++) {
                uint32_t b0 = buf + (uint32_t)(wm + 16 * mt + g) * 80u + kb;
                uint32_t b1 = b0 + 8u * 80u;
                a8f[mt][0] = lds32(b0);       a8f[mt][1] = lds32(b1);
                a8f[mt][2] = lds32(b0 + 16);  a8f[mt][3] = lds32(b1 + 16);
                al8f[mt][0] = lds32(b0 + 5120u);      al8f[mt][1] = lds32(b1 + 5120u);
                al8f[mt][2] = lds32(b0 + 5120u + 16); al8f[mt][3] = lds32(b1 + 5120u + 16);
            }
#pragma unroll
            for (int j = 0; j < 4; j++) {
                uint32_t nb = buf + 10240u + (uint32_t)(wn + 8 * j + g) * 80u + kb;
                uint32_t bl[2] = { lds32(nb),          lds32(nb + 16) };
                uint32_t bh[2] = { lds32(nb + 10240u), lds32(nb + 10240u + 16) };
#pragma unroll
                for (int mt = 0; mt < 2; mt++) {
                    mma8(acc[mt][j], a8f[mt], bl);
                    mma8(acc[mt][j], al8f[mt], bh);
                }
            }
        }

        if (kt + 2 < NT) {
            const uint32_t bo = (uint32_t)((kt + 2) % 3) * CSS;
            const int lk = (kt + 2) * 64;
            cpa16(sb + bo + adst,          A8g  + aoff + lk);
            cpa16(sb + bo + adst + 5120u,  AL8g + aoff + lk);
#pragma unroll
            for (int i = 0; i < 2; i++) {
                cpa16(sb + bo + wdst[i],           WL8g + woff[i] + lk);
                cpa16(sb + bo + wdst[i] + 10240u,  WH8g + woff[i] + lk);
            }
        }
        asm volatile("cp.async.commit_group;" ::: "memory");
    }

    const float sc = 1.f / 8192.f;
#pragma unroll
    for (int mt = 0; mt < 2; mt++) {
        const int row = m0 + wm + 16 * mt + g;
#pragma unroll
        for (int j = 0; j < 4; j++) {
            const int col = n0 + wn + 8 * j + 2 * tg;
            long long off = (long long)row * N + col;
            float2 c0 = *(const float2*)(C + off);
            *(float2*)(C + off) = make_float2(c0.x + acc[mt][j][0] * sc,
                                              c0.y + acc[mt][j][1] * sc);
            long long off1 = off + (long long)8 * N;
            float2 c1 = *(const float2*)(C + off1);
            *(float2*)(C + off1) = make_float2(c1.x + acc[mt][j][2] * sc,
                                               c1.y + acc[mt][j][3] * sc);
        }
    }
}

// ---------------- embedding gather ----------------
__global__ void embed_kernel(const int* __restrict__ idx,
                             const float* __restrict__ emb,
                             float* __restrict__ x)
{
    int row = blockIdx.x;
    int id  = idx[row];
    int t   = threadIdx.x;
    float4 v = *(const float4*)&emb[(long long)id * DIM + t * 4];
    *(float4*)&x[(long long)row * DIM + t * 4] = v;
}

// ---------------- rmsnorm -> fp16 (hi only) ----------------
__global__ void rmsnorm_h_kernel(const float* __restrict__ x,
                                 const float* __restrict__ w,
                                 __half* __restrict__ OH)
{
    __shared__ float red[8];
    int row = blockIdx.x;
    int t   = threadIdx.x;
    const float4* xr = (const float4*)(x + (long long)row * DIM);
    float4 v = xr[t];
    float ss = v.x * v.x + v.y * v.y + v.z * v.z + v.w * v.w;
#pragma unroll
    for (int o = 16; o > 0; o >>= 1) ss += __shfl_xor_sync(0xffffffffu, ss, o);
    if ((t & 31) == 0) red[t >> 5] = ss;
    __syncthreads();
    float tot = red[0] + red[1] + red[2] + red[3] + red[4] + red[5] + red[6] + red[7];
    float r = rsqrtf(tot * (1.f / (float)DIM) + 1e-6f);
    float4 wv = ((const float4*)w)[t];
    ((uint2*)(OH + (long long)row * DIM))[t] =
        make_uint2(pkh2(v.x * r * wv.x, v.y * r * wv.y),
                   pkh2(v.z * r * wv.z, v.w * r * wv.w));
}

// ======== flash attention on tensor cores (HD=64, fp16 hi/lo, 3-pass MMA) ========
// Inputs pre-split fp16 hi/lo. Output: fp16 hi + fp8 streams for o-correction.
#define FQH 0
#define FQL 8192
#define FKH 16384
#define FKL 24576
#define FVH 32768
#define FVL 40960
__device__ __forceinline__ uint32_t fsw(int row, int cbyte) {
    return (uint32_t)(row * 128 + (cbyte ^ ((row & 7) << 4)));
}
__global__ void __launch_bounds__(128) flash_mma(const __half* __restrict__ qh,
                                                 const __half* __restrict__ ql,
                                                 __half* __restrict__ OH,
                                                 unsigned char* __restrict__ A8,
                                                 unsigned char* __restrict__ AL8)
{
    __shared__ char sm[49152];
    const uint32_t sb = smem_u32(sm);
    const int qb  = blockIdx.x * 64;
    const int hh  = blockIdx.y;
    const int b   = blockIdx.z;
    const int tid = threadIdx.x;
    const int lane = tid & 31;
    const int wq  = tid >> 5;
    const long long base = (long long)b * SEQT * T3D + hh * 64;

#pragma unroll
    for (int u = 0; u < 4; u++) {
        int slot = u * 128 + tid;
        int r = slot >> 3, c = slot & 7;
        long long go = base + (long long)(qb + r) * T3D + c * 8;
        uint32_t dst = sb + FQH + fsw(r, c * 16);
        cpa16(dst, qh + go);
        cpa16(dst + (FQL - FQH), ql + go);
    }

    const int g   = lane >> 2;
    const int tg  = lane & 3;
    const int lrow = ((lane >> 3) & 1) * 8 + (lane & 7);
    const uint32_t lcol = ((uint32_t)lane >> 4) * 16;

    float o[8][4];
#pragma unroll
    for (int j = 0; j < 8; j++)
#pragma unroll
        for (int e = 0; e < 4; e++) o[j][e] = 0.f;
    float m0 = -1e30f, m1 = -1e30f, l0 = 0.f, l1 = 0.f;

    for (int k0 = 0; k0 <= qb; k0 += 64) {
        __syncthreads();
#pragma unroll
        for (int u = 0; u < 4; u++) {
            int slot = u * 128 + tid;
            int r = slot >> 3, c = slot & 7;
            long long go = base + (long long)(k0 + r) * T3D + DIM + c * 8;
            uint32_t sw = fsw(r, c * 16);
            uint32_t dk = sb + FKH + sw;
            cpa16(dk, qh + go);
            cpa16(dk + (FKL - FKH), ql + go);
            uint32_t dv = sb + FVH + sw;
            cpa16(dv, qh + go + DIM);
            cpa16(dv + (FVL - FVH), ql + go + DIM);
        }
        asm volatile("cp.async.wait_all;" ::: "memory");
        __syncthreads();

        float s[8][4];
#pragma unroll
        for (int j = 0; j < 8; j++)
#pragma unroll
            for (int e = 0; e < 4; e++) s[j][e] = 0.f;
#pragma unroll
        for (int sl = 0; sl < 4; sl++) {
            const uint32_t cb = (uint32_t)sl * 32;
            uint32_t qfh[4], qfl[4];
            {
                int ra = wq * 16 + lrow;
                uint32_t adr = sb + FQH + (uint32_t)ra * 128u + ((cb + lcol) ^ ((uint32_t)(ra & 7) << 4));
                ldm4(qfh, adr);
                ldm4(qfl, adr + (FQL - FQH));
            }
#pragma unroll
            for (int t = 0; t < 4; t++) {
                int rb = t * 16 + lrow;
                uint32_t adr = sb + FKH + (uint32_t)rb * 128u + ((cb + lcol) ^ ((uint32_t)(rb & 7) << 4));
                uint32_t kh[4], kl[4];
                ldm4(kh, adr);
                ldm4(kl, adr + (FKL - FKH));
#pragma unroll
                for (int e = 0; e < 2; e++) {
                    uint32_t bh[2] = { kh[e], kh[e + 2] };
                    uint32_t bl[2] = { kl[e], kl[e + 2] };
                    mma16816(s[2 * t + e], qfh, bh);
                    mma16816(s[2 * t + e], qfh, bl);
                    mma16816(s[2 * t + e], qfl, bh);
                }
            }
        }
#pragma unroll
        for (int j = 0; j < 8; j++)
#pragma unroll
            for (int e = 0; e < 4; e++) s[j][e] *= 0.125f;

        if (k0 + 64 > qb) {
            const int q0 = qb + wq * 16 + g;
#pragma unroll
            for (int j = 0; j < 8; j++) {
                int key = k0 + 8 * j + 2 * tg;
                if (key     > q0)     s[j][0] = -1e30f;
                if (key + 1 > q0)     s[j][1] = -1e30f;
                if (key     > q0 + 8) s[j][2] = -1e30f;
                if (key + 1 > q0 + 8) s[j][3] = -1e30f;
            }
        }

        float mx0 = -1e30f, mx1 = -1e30f;
#pragma unroll
        for (int j = 0; j < 8; j++) {
            mx0 = fmaxf(mx0, fmaxf(s[j][0], s[j][1]));
            mx1 = fmaxf(mx1, fmaxf(s[j][2], s[j][3]));
        }
        mx0 = fmaxf(mx0, __shfl_xor_sync(0xffffffffu, mx0, 1));
        mx0 = fmaxf(mx0, __shfl_xor_sync(0xffffffffu, mx0, 2));
        mx1 = fmaxf(mx1, __shfl_xor_sync(0xffffffffu, mx1, 1));
        mx1 = fmaxf(mx1, __shfl_xor_sync(0xffffffffu, mx1, 2));
        const float mn0 = fmaxf(m0, mx0), mn1 = fmaxf(m1, mx1);
        const float c0 = __expf(m0 - mn0), c1 = __expf(m1 - mn1);
        float ls0 = 0.f, ls1 = 0.f;
        uint32_t ph[8][2], pl[8][2];
#pragma unroll
        for (int j = 0; j < 8; j++) {
            float p0 = __expf(s[j][0] - mn0);
            float p1 = __expf(s[j][1] - mn0);
            float p2 = __expf(s[j][2] - mn1);
            float p3 = __expf(s[j][3] - mn1);
            ls0 += p0 + p1; ls1 += p2 + p3;
            split2h(p0, p1, ph[j][0], pl[j][0]);
            split2h(p2, p3, ph[j][1], pl[j][1]);
        }
        ls0 += __shfl_xor_sync(0xffffffffu, ls0, 1);
        ls0 += __shfl_xor_sync(0xffffffffu, ls0, 2);
        ls1 += __shfl_xor_sync(0xffffffffu, ls1, 1);
        ls1 += __shfl_xor_sync(0xffffffffu, ls1, 2);
        l0 = l0 * c0 + ls0; l1 = l1 * c1 + ls1;
        m0 = mn0; m1 = mn1;
#pragma unroll
        for (int j = 0; j < 8; j++) {
            o[j][0] *= c0; o[j][1] *= c0;
            o[j][2] *= c1; o[j][3] *= c1;
        }

#pragma unroll
        for (int sl = 0; sl < 4; sl++) {
            uint32_t ah[4] = { ph[2 * sl][0], ph[2 * sl][1], ph[2 * sl + 1][0], ph[2 * sl + 1][1] };
            uint32_t al[4] = { pl[2 * sl][0], pl[2 * sl][1], pl[2 * sl + 1][0], pl[2 * sl + 1][1] };
#pragma unroll
            for (int t = 0; t < 4; t++) {
                int rv = sl * 16 + lrow;
                uint32_t adr = sb + FVH + (uint32_t)rv * 128u +
                               (((uint32_t)t * 32 + lcol) ^ ((uint32_t)(rv & 7) << 4));
                uint32_t vh[4], vl[4];
                ldm4t(vh, adr);
                ldm4t(vl, adr + (FVL - FVH));
#pragma unroll
                for (int e = 0; e < 2; e++) {
                    uint32_t bh[2] = { vh[2 * e], vh[2 * e + 1] };
                    uint32_t bl[2] = { vl[2 * e], vl[2 * e + 1] };
                    mma16816(o[2 * t + e], ah, bh);
                    mma16816(o[2 * t + e], ah, bl);
                    mma16816(o[2 * t + e], al, bh);
                }
            }
        }
    }

    const float i0 = 1.f / l0, i1 = 1.f / l1;
    const int row0 = qb + wq * 16 + g;
#pragma unroll
    for (int j = 0; j < 8; j++) {
        const int col = hh * 64 + 8 * j + 2 * tg;
        long long off0 = ((long long)b * SEQT + row0) * DIM + col;
        long long off1 = off0 + (long long)8 * DIM;
        float v0 = o[j][0] * i0, v1 = o[j][1] * i0;
        float v2 = o[j][2] * i1, v3 = o[j][3] * i1;
        __half2 h01 = __floats2half2_rn(v0, v1);
        __half2 h23 = __floats2half2_rn(v2, v3);
        *(uint32_t*)(OH + off0) = *reinterpret_cast<uint32_t*>(&h01);
        *(uint32_t*)(OH + off1) = *reinterpret_cast<uint32_t*>(&h23);
        *(uint16_t*)(A8 + off0) = pk8(v0, v1);
        *(uint16_t*)(A8 + off1) = pk8(v2, v3);
        *(uint16_t*)(AL8 + off0) = pk8((v0 - __half2float(h01.x)) * 512.f,
                                       (v1 - __half2float(h01.y)) * 512.f);
        *(uint16_t*)(AL8 + off1) = pk8((v2 - __half2float(h23.x)) * 512.f,
                                       (v3 - __half2float(h23.y)) * 512.f);
    }
}

// ---------------- launch ----------------
#define GEMM_SMEM (4 * 24576 + 1024)
#define CORR_SMEM (3 * 30720 + 1024)

static inline void conv_launch(const float* s, __half* H, long long n) {
    conv_kernel<<<(unsigned)((n / 4 + 255) / 256), 256>>>(s, H, n);
}

extern "C" void kernel_launch(void* const* d_in, const int* in_sizes, int n_in,
                              void* d_out, int out_size)
{
    (void)in_sizes; (void)n_in; (void)out_size;
    const int*   idx  = (const int*)d_in[0];
    const float* emb  = (const float*)d_in[1];
    const float* ln1  = (const float*)d_in[2];
    const float* qkvw = (const float*)d_in[3];
    const float* ow   = (const float*)d_in[4];
    const float* ln2  = (const float*)d_in[5];
    const float* gw   = (const float*)d_in[6];
    const float* uw   = (const float*)d_in[7];
    const float* dw   = (const float*)d_in[8];
    const float* lnf  = (const float*)d_in[9];

    float *x, *gate;
    __half *q3h, *q3l, *hh, *a2h;
    __half *qkvh, *owh, *gwh, *uwh, *dwh, *embh;
    unsigned char *a8, *al8, *m8, *ml8, *owl8, *owh8, *dwl8, *dwh8;
    cudaGetSymbolAddress((void**)&x,    g_x);
    cudaGetSymbolAddress((void**)&gate, g_gate);
    cudaGetSymbolAddress((void**)&q3h,  g_q3h);
    cudaGetSymbolAddress((void**)&q3l,  g_q3l);
    cudaGetSymbolAddress((void**)&hh,   g_hh);
    cudaGetSymbolAddress((void**)&a2h,  g_2h);
    cudaGetSymbolAddress((void**)&a8,   g_a8);
    cudaGetSymbolAddress((void**)&al8,  g_al8);
    cudaGetSymbolAddress((void**)&m8,   g_m8);
    cudaGetSymbolAddress((void**)&ml8,  g_ml8);
    cudaGetSymbolAddress((void**)&qkvh, g_qkvh);
    cudaGetSymbolAddress((void**)&owh,  g_owh);
    cudaGetSymbolAddress((void**)&owl8, g_owl8);
    cudaGetSymbolAddress((void**)&owh8, g_owh8);
    cudaGetSymbolAddress((void**)&gwh,  g_gwh);
    cudaGetSymbolAddress((void**)&uwh,  g_uwh);
    cudaGetSymbolAddress((void**)&dwh,  g_dwh);
    cudaGetSymbolAddress((void**)&dwl8, g_dwl8);
    cudaGetSymbolAddress((void**)&dwh8, g_dwh8);
    cudaGetSymbolAddress((void**)&embh, g_embh);

    cudaFuncSetAttribute(gemm_p<0>, cudaFuncAttributeMaxDynamicSharedMemorySize, GEMM_SMEM);
    cudaFuncSetAttribute(gemm_p<1>, cudaFuncAttributeMaxDynamicSharedMemorySize, GEMM_SMEM);
    cudaFuncSetAttribute(gemm_p<2>, cudaFuncAttributeMaxDynamicSharedMemorySize, GEMM_SMEM);
    cudaFuncSetAttribute(gemm_p<3>, cudaFuncAttributeMaxDynamicSharedMemorySize, GEMM_SMEM);
    cudaFuncSetAttribute(corr8, cudaFuncAttributeMaxDynamicSharedMemorySize, CORR_SMEM);

    conv_launch(qkvw, qkvh, QKV_WN);                           // 0
    embed_kernel<<<BT, 256>>>(idx, emb, x);                    // 1

    for (int l = 0; l < NL; l++) {
        const __half* qw = qkvh + (long long)l * T3D * DIM;
        const __half* oh = owh + (long long)l * DIM * DIM;
        const __half* gh = gwh + (long long)l * DIFF * DIM;
        const __half* uh = uwh + (long long)l * DIFF * DIM;
        const __half* dh = dwh + (long long)l * DIM * DIFF;
        const long long ooff = (long long)l * DIM * DIM;
        const long long doff = (long long)l * DIM * DIFF;

        rmsnorm_h_kernel<<<BT, 256>>>(x, ln1 + (long long)l * DIM, hh);          // 2
        gemm_p<3><<<dim3(T3D / 128, BT / 64), 256, GEMM_SMEM>>>(                 // 3 <- profiled
            hh, qw, nullptr, q3h, q3l, nullptr, nullptr, T3D, DIM);
        if (l == 0) {
            conv_launch(gw, gwh, G_WN);
            conv_launch(uw, uwh, G_WN);
            conv_launch(emb, embh, E_WN);
            wsplit8_kernel<<<(unsigned)((O_WN / 4 + 255) / 256), 256>>>(ow, owh, owl8, owh8, O_WN);
            wsplit8_kernel<<<(unsigned)((D_WN / 4 + 255) / 256), 256>>>(dw, dwh, dwl8, dwh8, D_WN);
        }
        flash_mma<<<dim3(SEQT / 64, 16, 2), 128>>>(q3h, q3l, hh, a8, al8);
        gemm_p<1><<<dim3(DIM / 128, BT / 64), 256, GEMM_SMEM>>>(
            hh, oh, x, nullptr, nullptr, nullptr, nullptr, DIM, DIM);
        corr8<<<dim3(DIM / 128, BT / 64), 256, CORR_SMEM>>>(
            a8, al8, owl8 + ooff, owh8 + ooff, x, DIM, DIM);
        rmsnorm_h_kernel<<<BT, 256>>>(x, ln2 + (long long)l * DIM, hh);
        gemm_p<0><<<dim3(DIFF / 128, BT / 64), 256, GEMM_SMEM>>>(
            hh, gh, gate, nullptr, nullptr, nullptr, nullptr, DIFF, DIM);
        gemm_p<2><<<dim3(DIFF / 128, BT / 64), 256, GEMM_SMEM>>>(
            hh, uh, gate, a2h, nullptr, m8, ml8, DIFF, DIM);
        gemm_p<1><<<dim3(DIM / 128, BT / 64), 256, GEMM_SMEM>>>(
            a2h, dh, x, nullptr, nullptr, nullptr, nullptr, DIM, DIFF);
        corr8<<<dim3(DIM / 128, BT / 64), 256, CORR_SMEM>>>(
            m8, ml8, dwl8 + doff, dwh8 + doff, x, DIM, DIFF);
    }

    rmsnorm_h_kernel<<<BT, 256>>>(x, lnf, hh);
    gemm_p<0><<<dim3(NVOC / 128, BT / 64), 256, GEMM_SMEM>>>(
        hh, embh, (float*)d_out, nullptr, nullptr, nullptr, nullptr, NVOC, DIM);
}

// round 15
// speedup vs baseline: 1.1270x; 1.1270x over previous
#include <cuda_runtime.h>
#include <cuda_fp16.h>
#include <stdint.h>

// ---------------- problem constants ----------------
#define BT    4096        // B*T
#define SEQT  2048        // T
#define DIM   1024        // D
#define T3D   3072        // 3*D
#define DIFF  2048        // DI
#define NL    8           // layers
#define NVOC  32000       // vocab

#define QKV_WN ((long long)NL * T3D * DIM)
#define O_WN   ((long long)NL * DIM * DIM)
#define G_WN   ((long long)NL * DIFF * DIM)
#define D_WN   ((long long)NL * DIM * DIFF)
#define E_WN   ((long long)NVOC * DIM)

// ---------------- scratch ----------------
__device__ float g_x[BT * DIM];               // residual (fp32)
__device__ float g_gate[BT * DIFF];           // gate pre-act (fp32)
__device__ __half g_q3h[BT * T3D], g_q3l[BT * T3D]; // qkv hi/lo (fp16)
__device__ __half g_hh[BT * DIM],  g_hl[BT * DIM];   // activations hi/lo (fp16)
__device__ __half g_2h[BT * DIFF];                   // mlp mid (fp16, hi only)
// fp16 weights: hi for all; lo only where multi-pass (o, down)
__device__ __half g_qkvh[QKV_WN];
__device__ __half g_owh[O_WN],  g_owl[O_WN];
__device__ __half g_gwh[G_WN];
__device__ __half g_uwh[G_WN];
__device__ __half g_dwh[D_WN],  g_dwl[D_WN];
__device__ __half g_embh[E_WN];

// ---------------- helpers ----------------
__device__ __forceinline__ uint32_t smem_u32(const void* p) {
    uint32_t a;
    asm("{ .reg .u64 t; cvta.to.shared.u64 t, %1; cvt.u32.u64 %0, t; }" : "=r"(a) : "l"(p));
    return a;
}
__device__ __forceinline__ void ldm4(uint32_t* r, uint32_t a) {
    asm volatile("ldmatrix.sync.aligned.m8n8.x4.shared.b16 {%0,%1,%2,%3}, [%4];"
                 : "=r"(r[0]), "=r"(r[1]), "=r"(r[2]), "=r"(r[3]) : "r"(a));
}
__device__ __forceinline__ void ldm4t(uint32_t* r, uint32_t a) {
    asm volatile("ldmatrix.sync.aligned.m8n8.x4.trans.shared.b16 {%0,%1,%2,%3}, [%4];"
                 : "=r"(r[0]), "=r"(r[1]), "=r"(r[2]), "=r"(r[3]) : "r"(a));
}
__device__ __forceinline__ void mma16816(float* d, const uint32_t* a, const uint32_t* b) {
    asm volatile(
        "mma.sync.aligned.m16n8k16.row.col.f32.f16.f16.f32 "
        "{%0,%1,%2,%3}, {%4,%5,%6,%7}, {%8,%9}, {%0,%1,%2,%3};"
        : "+f"(d[0]), "+f"(d[1]), "+f"(d[2]), "+f"(d[3])
        : "r"(a[0]), "r"(a[1]), "r"(a[2]), "r"(a[3]), "r"(b[0]), "r"(b[1]));
}
__device__ __forceinline__ void cpa16(uint32_t d, const void* s) {
    asm volatile("cp.async.cg.shared.global [%0], [%1], 16;" :: "r"(d), "l"(s));
}
__device__ __forceinline__ uint32_t pkh2(float x, float y) {
    __half2 h = __floats2half2_rn(x, y);
    return *reinterpret_cast<uint32_t*>(&h);
}
__device__ __forceinline__ void split2h(float x, float y, uint32_t& h, uint32_t& l) {
    __half2 hb = __floats2half2_rn(x, y);
    h = *reinterpret_cast<uint32_t*>(&hb);
    l = pkh2(x - __half2float(__low2half(hb)), y - __half2float(__high2half(hb)));
}
__device__ __forceinline__ float silu_f(float x) { return x / (1.f + __expf(-x)); }

// ---------------- weight convert: fp32 -> fp16 (hi only) ----------------
__global__ void conv_kernel(const float* __restrict__ s,
                            __half* __restrict__ H, long long n)
{
    long long i = ((long long)blockIdx.x * 256 + threadIdx.x) * 4;
    if (i >= n) return;
    float4 v = *(const float4*)(s + i);
    *(uint2*)(H + i) = make_uint2(pkh2(v.x, v.y), pkh2(v.z, v.w));
}

// ---------------- weight split: fp32 -> fp16 hi + lo ----------------
__global__ void wsplit_kernel(const float* __restrict__ s,
                              __half* __restrict__ H,
                              __half* __restrict__ L, long long n)
{
    long long i = ((long long)blockIdx.x * 256 + threadIdx.x) * 4;
    if (i >= n) return;
    float4 v = *(const float4*)(s + i);
    uint32_t h0, l0, h1, l1;
    split2h(v.x, v.y, h0, l0);
    split2h(v.z, v.w, h1, l1);
    *(uint2*)(H + i) = make_uint2(h0, h1);
    *(uint2*)(L + i) = make_uint2(l0, l1);
}

// EPI 0: C=acc ; 1: C+=acc ; 2: OH=fp16(silu(C)*acc) (hi only) ;
// 3: OH/OL = fp16 hi/lo split(acc)
template <int EPI>
__device__ __forceinline__ void epi2(float* __restrict__ C,
                                     __half* __restrict__ OH,
                                     __half* __restrict__ OL,
                                     long long off, float x, float y)
{
    if (EPI == 0) {
        *(float2*)(C + off) = make_float2(x, y);
    } else if (EPI == 1) {
        float2 c = *(const float2*)(C + off);
        *(float2*)(C + off) = make_float2(c.x + x, c.y + y);
    } else if (EPI == 2) {
        float2 c = *(const float2*)(C + off);
        x = silu_f(c.x) * x;
        y = silu_f(c.y) * y;
        *(uint32_t*)(OH + off) = pkh2(x, y);
    } else {
        uint32_t h, l;
        split2h(x, y, h, l);
        *(uint32_t*)(OH + off) = h;
        *(uint32_t*)(OL + off) = l;
    }
}

// ============ unified multi-pass fp16 mma.sync GEMM ============
// C[M,N] = sum over passes p of Ap[M,K] @ Wp[N,K]^T  (fp32 accumulate).
// CTA tile 64x128, BK=64, 256 threads = 8 warps (2 M x 4 N, warp 32x32).
// Stage 24KB (A 8KB @0, W 16KB @8K), 4 stages = 96KB -> 2 CTAs/SM.
// Passes run sequentially over the K loop; accumulators persist.
#define GSS 24576u
template <int NPASS, int EPI>
__global__ void __launch_bounds__(256, 2) gemm_p(
    const __half* __restrict__ A0, const __half* __restrict__ A1,
    const __half* __restrict__ A2,
    const __half* __restrict__ W0, const __half* __restrict__ W1,
    const __half* __restrict__ W2,
    float* __restrict__ C, __half* __restrict__ OH, __half* __restrict__ OL,
    int N, int K)
{
    extern __shared__ char dsm_raw[];
    char* dsm = (char*)(((uintptr_t)dsm_raw + 1023) & ~(uintptr_t)1023);
    const uint32_t sb = smem_u32(dsm);

    const int tid = threadIdx.x;
    const int wid = tid >> 5;
    const int lane = tid & 31;
    const int m0 = blockIdx.y * 64;
    const int n0 = blockIdx.x * 128;

    const int prow = tid >> 3;
    const int pcc  = tid & 7;
    const long long aoff = (long long)(m0 + prow) * K + pcc * 8;
    const long long woff = (long long)(n0 + prow) * K + pcc * 8;
    const uint32_t pdst = (uint32_t)prow * 128u +
                          (((uint32_t)pcc * 16u) ^ ((uint32_t)(prow & 7) << 4));
    const uint32_t dA = sb + pdst;
    const uint32_t dW = sb + 8192u + pdst;

    const int wm = (wid >> 2) * 32;
    const int wn = (wid & 3) * 32;
    const int lrow = ((lane >> 3) & 1) * 8 + (lane & 7);
    const uint32_t lcol = ((uint32_t)lane >> 4) * 16;
    uint32_t aOff[2], aXor[2], bOff[2], bXor[2];
#pragma unroll
    for (int t = 0; t < 2; t++) {
        int ra = wm + t * 16 + lrow;
        aOff[t] = (uint32_t)ra * 128u; aXor[t] = (uint32_t)(ra & 7) << 4;
        int rb = wn + t * 16 + lrow;
        bOff[t] = 8192u + (uint32_t)rb * 128u; bXor[t] = (uint32_t)(rb & 7) << 4;
    }

    float acc[2][4][4];
#pragma unroll
    for (int i = 0; i < 2; i++)
#pragma unroll
        for (int j = 0; j < 4; j++)
#pragma unroll
            for (int k = 0; k < 4; k++) acc[i][j][k] = 0.f;

    const int NT = K >> 6;
    const int TT = NPASS * NT;
    int lp = 0, lk = 0;    // load-stream tracker: pass, k-offset (elements)

#pragma unroll
    for (int st = 0; st < 3; st++) {
        if (st < TT) {
            const __half* cA = (NPASS == 1 || lp == 0) ? A0 : (lp == 1 ? A1 : A2);
            const __half* cW = (NPASS == 1 || lp == 0) ? W0 : (lp == 1 ? W1 : W2);
            const uint32_t bo = (uint32_t)st * GSS;
            cpa16(dA + bo,          cA + aoff + lk);
            cpa16(dA + bo + 4096u,  cA + aoff + (long long)32 * K + lk);
#pragma unroll
            for (int i = 0; i < 4; i++)
                cpa16(dW + bo + 4096u * i, cW + woff + (long long)32 * K * i + lk);
            lk += 64; if (lk == K) { lk = 0; lp++; }
        }
        asm volatile("cp.async.commit_group;" ::: "memory");
    }

    for (int kt = 0; kt < TT; kt++) {
        asm volatile("cp.async.wait_group 2;" ::: "memory");
        __syncthreads();
        const uint32_t buf = sb + (uint32_t)(kt & 3) * GSS;

#pragma unroll
        for (int s = 0; s < 4; s++) {
            const uint32_t cb = (uint32_t)s * 32;
            uint32_t ah[2][4], bh[2][4];
#pragma unroll
            for (int t = 0; t < 2; t++) {
                ldm4(ah[t], buf + aOff[t] + ((cb + lcol) ^ aXor[t]));
                ldm4(bh[t], buf + bOff[t] + ((cb + lcol) ^ bXor[t]));
            }
#pragma unroll
            for (int mt = 0; mt < 2; mt++)
#pragma unroll
                for (int n8 = 0; n8 < 4; n8++) {
                    uint32_t bf[2] = { bh[n8 >> 1][n8 & 1], bh[n8 >> 1][(n8 & 1) + 2] };
                    mma16816(acc[mt][n8], ah[mt], bf);
                }
        }

        if (kt + 3 < TT) {
            const __half* cA = (NPASS == 1 || lp == 0) ? A0 : (lp == 1 ? A1 : A2);
            const __half* cW = (NPASS == 1 || lp == 0) ? W0 : (lp == 1 ? W1 : W2);
            const uint32_t bo = (uint32_t)((kt + 3) & 3) * GSS;
            cpa16(dA + bo,          cA + aoff + lk);
            cpa16(dA + bo + 4096u,  cA + aoff + (long long)32 * K + lk);
#pragma unroll
            for (int i = 0; i < 4; i++)
                cpa16(dW + bo + 4096u * i, cW + woff + (long long)32 * K * i + lk);
            lk += 64; if (lk == K) { lk = 0; lp++; }
        }
        asm volatile("cp.async.commit_group;" ::: "memory");
    }

    const int er = lane >> 2;
    const int ec = (lane & 3) * 2;
#pragma unroll
    for (int mt = 0; mt < 2; mt++) {
        const int row = m0 + wm + mt * 16 + er;
#pragma unroll
        for (int n8 = 0; n8 < 4; n8++) {
            const int col = n0 + wn + n8 * 8 + ec;
            long long off = (long long)row * N + col;
            epi2<EPI>(C, OH, OL, off,                    acc[mt][n8][0], acc[mt][n8][1]);
            epi2<EPI>(C, OH, OL, off + (long long)8 * N, acc[mt][n8][2], acc[mt][n8][3]);
        }
    }
}

// ---------------- embedding gather ----------------
__global__ void embed_kernel(const int* __restrict__ idx,
                             const float* __restrict__ emb,
                             float* __restrict__ x)
{
    int row = blockIdx.x;
    int id  = idx[row];
    int t   = threadIdx.x;
    float4 v = *(const float4*)&emb[(long long)id * DIM + t * 4];
    *(float4*)&x[(long long)row * DIM + t * 4] = v;
}

// ---------------- rmsnorm -> fp16 (hi only) ----------------
__global__ void rmsnorm_h_kernel(const float* __restrict__ x,
                                 const float* __restrict__ w,
                                 __half* __restrict__ OH)
{
    __shared__ float red[8];
    int row = blockIdx.x;
    int t   = threadIdx.x;
    const float4* xr = (const float4*)(x + (long long)row * DIM);
    float4 v = xr[t];
    float ss = v.x * v.x + v.y * v.y + v.z * v.z + v.w * v.w;
#pragma unroll
    for (int o = 16; o > 0; o >>= 1) ss += __shfl_xor_sync(0xffffffffu, ss, o);
    if ((t & 31) == 0) red[t >> 5] = ss;
    __syncthreads();
    float tot = red[0] + red[1] + red[2] + red[3] + red[4] + red[5] + red[6] + red[7];
    float r = rsqrtf(tot * (1.f / (float)DIM) + 1e-6f);
    float4 wv = ((const float4*)w)[t];
    ((uint2*)(OH + (long long)row * DIM))[t] =
        make_uint2(pkh2(v.x * r * wv.x, v.y * r * wv.y),
                   pkh2(v.z * r * wv.z, v.w * r * wv.w));
}

// ======== flash attention on tensor cores (HD=64, fp16 hi/lo, 3-pass MMA) ========
// Inputs are PRE-SPLIT fp16 hi/lo (qkv written by the QKV GEMM epilogue).
#define FQH 0
#define FQL 8192
#define FKH 16384
#define FKL 24576
#define FVH 32768
#define FVL 40960
__device__ __forceinline__ uint32_t fsw(int row, int cbyte) {
    return (uint32_t)(row * 128 + (cbyte ^ ((row & 7) << 4)));
}
__global__ void __launch_bounds__(128) flash_mma(const __half* __restrict__ qh,
                                                 const __half* __restrict__ ql,
                                                 __half* __restrict__ OH,
                                                 __half* __restrict__ OL)
{
    __shared__ char sm[49152];
    const uint32_t sb = smem_u32(sm);
    const int qb  = blockIdx.x * 64;
    const int hh  = blockIdx.y;
    const int b   = blockIdx.z;
    const int tid = threadIdx.x;
    const int lane = tid & 31;
    const int wq  = tid >> 5;
    const long long base = (long long)b * SEQT * T3D + hh * 64;

#pragma unroll
    for (int u = 0; u < 4; u++) {
        int slot = u * 128 + tid;
        int r = slot >> 3, c = slot & 7;
        long long go = base + (long long)(qb + r) * T3D + c * 8;
        uint32_t dst = sb + FQH + fsw(r, c * 16);
        cpa16(dst, qh + go);
        cpa16(dst + (FQL - FQH), ql + go);
    }

    const int g   = lane >> 2;
    const int tg  = lane & 3;
    const int lrow = ((lane >> 3) & 1) * 8 + (lane & 7);
    const uint32_t lcol = ((uint32_t)lane >> 4) * 16;

    float o[8][4];
#pragma unroll
    for (int j = 0; j < 8; j++)
#pragma unroll
        for (int e = 0; e < 4; e++) o[j][e] = 0.f;
    float m0 = -1e30f, m1 = -1e30f, l0 = 0.f, l1 = 0.f;

    for (int k0 = 0; k0 <= qb; k0 += 64) {
        __syncthreads();
#pragma unroll
        for (int u = 0; u < 4; u++) {
            int slot = u * 128 + tid;
            int r = slot >> 3, c = slot & 7;
            long long go = base + (long long)(k0 + r) * T3D + DIM + c * 8;
            uint32_t sw = fsw(r, c * 16);
            uint32_t dk = sb + FKH + sw;
            cpa16(dk, qh + go);
            cpa16(dk + (FKL - FKH), ql + go);
            uint32_t dv = sb + FVH + sw;
            cpa16(dv, qh + go + DIM);
            cpa16(dv + (FVL - FVH), ql + go + DIM);
        }
        asm volatile("cp.async.wait_all;" ::: "memory");
        __syncthreads();

        float s[8][4];
#pragma unroll
        for (int j = 0; j < 8; j++)
#pragma unroll
            for (int e = 0; e < 4; e++) s[j][e] = 0.f;
#pragma unroll
        for (int sl = 0; sl < 4; sl++) {
            const uint32_t cb = (uint32_t)sl * 32;
            uint32_t qfh[4], qfl[4];
            {
                int ra = wq * 16 + lrow;
                uint32_t adr = sb + FQH + (uint32_t)ra * 128u + ((cb + lcol) ^ ((uint32_t)(ra & 7) << 4));
                ldm4(qfh, adr);
                ldm4(qfl, adr + (FQL - FQH));
            }
#pragma unroll
            for (int t = 0; t < 4; t++) {
                int rb = t * 16 + lrow;
                uint32_t adr = sb + FKH + (uint32_t)rb * 128u + ((cb + lcol) ^ ((uint32_t)(rb & 7) << 4));
                uint32_t kh[4], kl[4];
                ldm4(kh, adr);
                ldm4(kl, adr + (FKL - FKH));
#pragma unroll
                for (int e = 0; e < 2; e++) {
                    uint32_t bh[2] = { kh[e], kh[e + 2] };
                    uint32_t bl[2] = { kl[e], kl[e + 2] };
                    mma16816(s[2 * t + e], qfh, bh);
                    mma16816(s[2 * t + e], qfh, bl);
                    mma16816(s[2 * t + e], qfl, bh);
                }
            }
        }
#pragma unroll
        for (int j = 0; j < 8; j++)
#pragma unroll
            for (int e = 0; e < 4; e++) s[j][e] *= 0.125f;

        if (k0 + 64 > qb) {
            const int q0 = qb + wq * 16 + g;
#pragma unroll
            for (int j = 0; j < 8; j++) {
                int key = k0 + 8 * j + 2 * tg;
                if (key     > q0)     s[j][0] = -1e30f;
                if (key + 1 > q0)     s[j][1] = -1e30f;
                if (key     > q0 + 8) s[j][2] = -1e30f;
                if (key + 1 > q0 + 8) s[j][3] = -1e30f;
            }
        }

        float mx0 = -1e30f, mx1 = -1e30f;
#pragma unroll
        for (int j = 0; j < 8; j++) {
            mx0 = fmaxf(mx0, fmaxf(s[j][0], s[j][1]));
            mx1 = fmaxf(mx1, fmaxf(s[j][2], s[j][3]));
        }
        mx0 = fmaxf(mx0, __shfl_xor_sync(0xffffffffu, mx0, 1));
        mx0 = fmaxf(mx0, __shfl_xor_sync(0xffffffffu, mx0, 2));
        mx1 = fmaxf(mx1, __shfl_xor_sync(0xffffffffu, mx1, 1));
        mx1 = fmaxf(mx1, __shfl_xor_sync(0xffffffffu, mx1, 2));
        const float mn0 = fmaxf(m0, mx0), mn1 = fmaxf(m1, mx1);
        const float c0 = __expf(m0 - mn0), c1 = __expf(m1 - mn1);
        float ls0 = 0.f, ls1 = 0.f;
        uint32_t ph[8][2], pl[8][2];
#pragma unroll
        for (int j = 0; j < 8; j++) {
            float p0 = __expf(s[j][0] - mn0);
            float p1 = __expf(s[j][1] - mn0);
            float p2 = __expf(s[j][2] - mn1);
            float p3 = __expf(s[j][3] - mn1);
            ls0 += p0 + p1; ls1 += p2 + p3;
            split2h(p0, p1, ph[j][0], pl[j][0]);
            split2h(p2, p3, ph[j][1], pl[j][1]);
        }
        ls0 += __shfl_xor_sync(0xffffffffu, ls0, 1);
        ls0 += __shfl_xor_sync(0xffffffffu, ls0, 2);
        ls1 += __shfl_xor_sync(0xffffffffu, ls1, 1);
        ls1 += __shfl_xor_sync(0xffffffffu, ls1, 2);
        l0 = l0 * c0 + ls0; l1 = l1 * c1 + ls1;
        m0 = mn0; m1 = mn1;
#pragma unroll
        for (int j = 0; j < 8; j++) {
            o[j][0] *= c0; o[j][1] *= c0;
            o[j][2] *= c1; o[j][3] *= c1;
        }

#pragma unroll
        for (int sl = 0; sl < 4; sl++) {
            uint32_t ah[4] = { ph[2 * sl][0], ph[2 * sl][1], ph[2 * sl + 1][0], ph[2 * sl + 1][1] };
            uint32_t al[4] = { pl[2 * sl][0], pl[2 * sl][1], pl[2 * sl + 1][0], pl[2 * sl + 1][1] };
#pragma unroll
            for (int t = 0; t < 4; t++) {
                int rv = sl * 16 + lrow;
                uint32_t adr = sb + FVH + (uint32_t)rv * 128u +
                               (((uint32_t)t * 32 + lcol) ^ ((uint32_t)(rv & 7) << 4));
                uint32_t vh[4], vl[4];
                ldm4t(vh, adr);
                ldm4t(vl, adr + (FVL - FVH));
#pragma unroll
                for (int e = 0; e < 2; e++) {
                    uint32_t bh[2] = { vh[2 * e], vh[2 * e + 1] };
                    uint32_t bl[2] = { vl[2 * e], vl[2 * e + 1] };
                    mma16816(o[2 * t + e], ah, bh);
                    mma16816(o[2 * t + e], ah, bl);
                    mma16816(o[2 * t + e], al, bh);
                }
            }
        }
    }

    const float i0 = 1.f / l0, i1 = 1.f / l1;
    const int row0 = qb + wq * 16 + g;
#pragma unroll
    for (int j = 0; j < 8; j++) {
        const int col = hh * 64 + 8 * j + 2 * tg;
        long long off0 = ((long long)b * SEQT + row0) * DIM + col;
        long long off1 = off0 + (long long)8 * DIM;
        uint32_t h, l;
        split2h(o[j][0] * i0, o[j][1] * i0, h, l);
        *(uint32_t*)(OH + off0) = h;
        *(uint32_t*)(OL + off0) = l;
        split2h(o[j][2] * i1, o[j][3] * i1, h, l);
        *(uint32_t*)(OH + off1) = h;
        *(uint32_t*)(OL + off1) = l;
    }
}

// ---------------- launch ----------------
#define GEMM_SMEM (4 * 24576 + 1024)

static inline void conv_launch(const float* s, __half* H, long long n) {
    conv_kernel<<<(unsigned)((n / 4 + 255) / 256), 256>>>(s, H, n);
}
static inline void wsplit_launch(const float* s, __half* H, __half* L, long long n) {
    wsplit_kernel<<<(unsigned)((n / 4 + 255) / 256), 256>>>(s, H, L, n);
}

extern "C" void kernel_launch(void* const* d_in, const int* in_sizes, int n_in,
                              void* d_out, int out_size)
{
    (void)in_sizes; (void)n_in; (void)out_size;
    const int*   idx  = (const int*)d_in[0];
    const float* emb  = (const float*)d_in[1];
    const float* ln1  = (const float*)d_in[2];
    const float* qkvw = (const float*)d_in[3];
    const float* ow   = (const float*)d_in[4];
    const float* ln2  = (const float*)d_in[5];
    const float* gw   = (const float*)d_in[6];
    const float* uw   = (const float*)d_in[7];
    const float* dw   = (const float*)d_in[8];
    const float* lnf  = (const float*)d_in[9];

    float *x, *gate;
    __half *q3h, *q3l, *hh, *hl, *a2h;
    __half *qkvh, *owh, *owl, *gwh, *uwh, *dwh, *dwl, *embh;
    cudaGetSymbolAddress((void**)&x,    g_x);
    cudaGetSymbolAddress((void**)&gate, g_gate);
    cudaGetSymbolAddress((void**)&q3h,  g_q3h);
    cudaGetSymbolAddress((void**)&q3l,  g_q3l);
    cudaGetSymbolAddress((void**)&hh,   g_hh);
    cudaGetSymbolAddress((void**)&hl,   g_hl);
    cudaGetSymbolAddress((void**)&a2h,  g_2h);
    cudaGetSymbolAddress((void**)&qkvh, g_qkvh);
    cudaGetSymbolAddress((void**)&owh,  g_owh);
    cudaGetSymbolAddress((void**)&owl,  g_owl);
    cudaGetSymbolAddress((void**)&gwh,  g_gwh);
    cudaGetSymbolAddress((void**)&uwh,  g_uwh);
    cudaGetSymbolAddress((void**)&dwh,  g_dwh);
    cudaGetSymbolAddress((void**)&dwl,  g_dwl);
    cudaGetSymbolAddress((void**)&embh, g_embh);

    cudaFuncSetAttribute(gemm_p<1,0>, cudaFuncAttributeMaxDynamicSharedMemorySize, GEMM_SMEM);
    cudaFuncSetAttribute(gemm_p<1,2>, cudaFuncAttributeMaxDynamicSharedMemorySize, GEMM_SMEM);
    cudaFuncSetAttribute(gemm_p<1,3>, cudaFuncAttributeMaxDynamicSharedMemorySize, GEMM_SMEM);
    cudaFuncSetAttribute(gemm_p<2,1>, cudaFuncAttributeMaxDynamicSharedMemorySize, GEMM_SMEM);
    cudaFuncSetAttribute(gemm_p<3,1>, cudaFuncAttributeMaxDynamicSharedMemorySize, GEMM_SMEM);

    conv_launch(qkvw, qkvh, QKV_WN);                           // 0
    embed_kernel<<<BT, 256>>>(idx, emb, x);                    // 1

    for (int l = 0; l < NL; l++) {
        const __half* qw = qkvh + (long long)l * T3D * DIM;
        const __half* oh = owh + (long long)l * DIM * DIM;
        const __half* ol = owl + (long long)l * DIM * DIM;
        const __half* gh = gwh + (long long)l * DIFF * DIM;
        const __half* uh = uwh + (long long)l * DIFF * DIM;
        const __half* dh = dwh + (long long)l * DIM * DIFF;
        const __half* dl = dwl + (long long)l * DIM * DIFF;

        rmsnorm_h_kernel<<<BT, 256>>>(x, ln1 + (long long)l * DIM, hh);          // 2
        gemm_p<1,3><<<dim3(T3D / 128, BT / 64), 256, GEMM_SMEM>>>(               // 3 <- profiled
            hh, nullptr, nullptr, qw, nullptr, nullptr,
            nullptr, q3h, q3l, T3D, DIM);
        if (l == 0) {
            conv_launch(gw, gwh, G_WN);
            conv_launch(uw, uwh, G_WN);
            conv_launch(emb, embh, E_WN);
            wsplit_launch(ow, owh, owl, O_WN);
            wsplit_launch(dw, dwh, dwl, D_WN);
        }
        flash_mma<<<dim3(SEQT / 64, 16, 2), 128>>>(q3h, q3l, hh, hl);
        gemm_p<3,1><<<dim3(DIM / 128, BT / 64), 256, GEMM_SMEM>>>(
            hh, hh, hl, oh, ol, oh,
            x, nullptr, nullptr, DIM, DIM);
        rmsnorm_h_kernel<<<BT, 256>>>(x, ln2 + (long long)l * DIM, hh);
        gemm_p<1,0><<<dim3(DIFF / 128, BT / 64), 256, GEMM_SMEM>>>(
            hh, nullptr, nullptr, gh, nullptr, nullptr,
            gate, nullptr, nullptr, DIFF, DIM);
        gemm_p<1,2><<<dim3(DIFF / 128, BT / 64), 256, GEMM_SMEM>>>(
            hh, nullptr, nullptr, uh, nullptr, nullptr,
            gate, a2h, nullptr, DIFF, DIM);
        // down-proj: 2-pass (act hi only) -> a2h*(dwh + dwl)
        gemm_p<2,1><<<dim3(DIM / 128, BT / 64), 256, GEMM_SMEM>>>(
            a2h, a2h, nullptr, dh, dl, nullptr,
            x, nullptr, nullptr, DIM, DIFF);
    }

    rmsnorm_h_kernel<<<BT, 256>>>(x, lnf, hh);
    gemm_p<1,0><<<dim3(NVOC / 128, BT / 64), 256, GEMM_SMEM>>>(
        hh, nullptr, nullptr, embh, nullptr, nullptr,
        (float*)d_out, nullptr, nullptr, NVOC, DIM);
}

// round 16
// speedup vs baseline: 1.1717x; 1.0397x over previous
#include <cuda_runtime.h>
#include <cuda_fp16.h>
#include <stdint.h>

// ---------------- problem constants ----------------
#define BT    4096        // B*T
#define SEQT  2048        // T
#define DIM   1024        // D
#define T3D   3072        // 3*D
#define DIFF  2048        // DI
#define NL    8           // layers
#define NVOC  32000       // vocab

#define QKV_WN ((long long)NL * T3D * DIM)
#define O_WN   ((long long)NL * DIM * DIM)
#define G_WN   ((long long)NL * DIFF * DIM)
#define D_WN   ((long long)NL * DIM * DIFF)
#define E_WN   ((long long)NVOC * DIM)

// ---------------- scratch ----------------
__device__ float g_x[BT * DIM];               // residual (fp32)
__device__ float g_gate[BT * DIFF];           // gate pre-act (fp32)
__device__ __half g_q3h[BT * T3D], g_q3l[BT * T3D]; // qkv hi/lo (fp16)
__device__ __half g_hh[BT * DIM];             // activations (fp16, hi only)
__device__ __half g_2h[BT * DIFF];            // mlp mid (fp16, hi only)
// fp16 weights: hi for all; lo only where multi-pass (o, down)
__device__ __half g_qkvh[QKV_WN];
__device__ __half g_owh[O_WN],  g_owl[O_WN];
__device__ __half g_gwh[G_WN];
__device__ __half g_uwh[G_WN];
__device__ __half g_dwh[D_WN],  g_dwl[D_WN];
__device__ __half g_embh[E_WN];

// ---------------- helpers ----------------
__device__ __forceinline__ uint32_t smem_u32(const void* p) {
    uint32_t a;
    asm("{ .reg .u64 t; cvta.to.shared.u64 t, %1; cvt.u32.u64 %0, t; }" : "=r"(a) : "l"(p));
    return a;
}
__device__ __forceinline__ void ldm4(uint32_t* r, uint32_t a) {
    asm volatile("ldmatrix.sync.aligned.m8n8.x4.shared.b16 {%0,%1,%2,%3}, [%4];"
                 : "=r"(r[0]), "=r"(r[1]), "=r"(r[2]), "=r"(r[3]) : "r"(a));
}
__device__ __forceinline__ void ldm4t(uint32_t* r, uint32_t a) {
    asm volatile("ldmatrix.sync.aligned.m8n8.x4.trans.shared.b16 {%0,%1,%2,%3}, [%4];"
                 : "=r"(r[0]), "=r"(r[1]), "=r"(r[2]), "=r"(r[3]) : "r"(a));
}
__device__ __forceinline__ void mma16816(float* d, const uint32_t* a, const uint32_t* b) {
    asm volatile(
        "mma.sync.aligned.m16n8k16.row.col.f32.f16.f16.f32 "
        "{%0,%1,%2,%3}, {%4,%5,%6,%7}, {%8,%9}, {%0,%1,%2,%3};"
        : "+f"(d[0]), "+f"(d[1]), "+f"(d[2]), "+f"(d[3])
        : "r"(a[0]), "r"(a[1]), "r"(a[2]), "r"(a[3]), "r"(b[0]), "r"(b[1]));
}
__device__ __forceinline__ void cpa16(uint32_t d, const void* s) {
    asm volatile("cp.async.cg.shared.global [%0], [%1], 16;" :: "r"(d), "l"(s));
}
__device__ __forceinline__ uint32_t pkh2(float x, float y) {
    __half2 h = __floats2half2_rn(x, y);
    return *reinterpret_cast<uint32_t*>(&h);
}
__device__ __forceinline__ void split2h(float x, float y, uint32_t& h, uint32_t& l) {
    __half2 hb = __floats2half2_rn(x, y);
    h = *reinterpret_cast<uint32_t*>(&hb);
    l = pkh2(x - __half2float(__low2half(hb)), y - __half2float(__high2half(hb)));
}
__device__ __forceinline__ float silu_f(float x) { return x / (1.f + __expf(-x)); }

// ---------------- weight convert: fp32 -> fp16 (hi only) ----------------
__global__ void conv_kernel(const float* __restrict__ s,
                            __half* __restrict__ H, long long n)
{
    long long i = ((long long)blockIdx.x * 256 + threadIdx.x) * 4;
    if (i >= n) return;
    float4 v = *(const float4*)(s + i);
    *(uint2*)(H + i) = make_uint2(pkh2(v.x, v.y), pkh2(v.z, v.w));
}

// ---------------- weight split: fp32 -> fp16 hi + lo ----------------
__global__ void wsplit_kernel(const float* __restrict__ s,
                              __half* __restrict__ H,
                              __half* __restrict__ L, long long n)
{
    long long i = ((long long)blockIdx.x * 256 + threadIdx.x) * 4;
    if (i >= n) return;
    float4 v = *(const float4*)(s + i);
    uint32_t h0, l0, h1, l1;
    split2h(v.x, v.y, h0, l0);
    split2h(v.z, v.w, h1, l1);
    *(uint2*)(H + i) = make_uint2(h0, h1);
    *(uint2*)(L + i) = make_uint2(l0, l1);
}

// EPI 0: C=acc ; 1: C+=acc ; 2: OH=fp16(silu(C)*acc) (hi only) ;
// 3: OH/OL = fp16 hi/lo split(acc)
template <int EPI>
__device__ __forceinline__ void epi2(float* __restrict__ C,
                                     __half* __restrict__ OH,
                                     __half* __restrict__ OL,
                                     long long off, float x, float y)
{
    if (EPI == 0) {
        *(float2*)(C + off) = make_float2(x, y);
    } else if (EPI == 1) {
        float2 c = *(const float2*)(C + off);
        *(float2*)(C + off) = make_float2(c.x + x, c.y + y);
    } else if (EPI == 2) {
        float2 c = *(const float2*)(C + off);
        x = silu_f(c.x) * x;
        y = silu_f(c.y) * y;
        *(uint32_t*)(OH + off) = pkh2(x, y);
    } else {
        uint32_t h, l;
        split2h(x, y, h, l);
        *(uint32_t*)(OH + off) = h;
        *(uint32_t*)(OL + off) = l;
    }
}

// ============ unified multi-pass fp16 mma.sync GEMM ============
// C[M,N] = sum over passes p of Ap[M,K] @ Wp[N,K]^T  (fp32 accumulate).
// CTA tile 64x128, BK=64, 256 threads = 8 warps (2 M x 4 N, warp 32x32).
// Stage 24KB (A 8KB @0, W 16KB @8K), 4 stages = 96KB -> 2 CTAs/SM.
// Passes run sequentially over the K loop; accumulators persist.
#define GSS 24576u
template <int NPASS, int EPI>
__global__ void __launch_bounds__(256, 2) gemm_p(
    const __half* __restrict__ A0, const __half* __restrict__ A1,
    const __half* __restrict__ A2,
    const __half* __restrict__ W0, const __half* __restrict__ W1,
    const __half* __restrict__ W2,
    float* __restrict__ C, __half* __restrict__ OH, __half* __restrict__ OL,
    int N, int K)
{
    extern __shared__ char dsm_raw[];
    char* dsm = (char*)(((uintptr_t)dsm_raw + 1023) & ~(uintptr_t)1023);
    const uint32_t sb = smem_u32(dsm);

    const int tid = threadIdx.x;
    const int wid = tid >> 5;
    const int lane = tid & 31;
    const int m0 = blockIdx.y * 64;
    const int n0 = blockIdx.x * 128;

    const int prow = tid >> 3;
    const int pcc  = tid & 7;
    const long long aoff = (long long)(m0 + prow) * K + pcc * 8;
    const long long woff = (long long)(n0 + prow) * K + pcc * 8;
    const uint32_t pdst = (uint32_t)prow * 128u +
                          (((uint32_t)pcc * 16u) ^ ((uint32_t)(prow & 7) << 4));
    const uint32_t dA = sb + pdst;
    const uint32_t dW = sb + 8192u + pdst;

    const int wm = (wid >> 2) * 32;
    const int wn = (wid & 3) * 32;
    const int lrow = ((lane >> 3) & 1) * 8 + (lane & 7);
    const uint32_t lcol = ((uint32_t)lane >> 4) * 16;
    uint32_t aOff[2], aXor[2], bOff[2], bXor[2];
#pragma unroll
    for (int t = 0; t < 2; t++) {
        int ra = wm + t * 16 + lrow;
        aOff[t] = (uint32_t)ra * 128u; aXor[t] = (uint32_t)(ra & 7) << 4;
        int rb = wn + t * 16 + lrow;
        bOff[t] = 8192u + (uint32_t)rb * 128u; bXor[t] = (uint32_t)(rb & 7) << 4;
    }

    float acc[2][4][4];
#pragma unroll
    for (int i = 0; i < 2; i++)
#pragma unroll
        for (int j = 0; j < 4; j++)
#pragma unroll
            for (int k = 0; k < 4; k++) acc[i][j][k] = 0.f;

    const int NT = K >> 6;
    const int TT = NPASS * NT;
    int lp = 0, lk = 0;    // load-stream tracker: pass, k-offset (elements)

#pragma unroll
    for (int st = 0; st < 3; st++) {
        if (st < TT) {
            const __half* cA = (NPASS == 1 || lp == 0) ? A0 : (lp == 1 ? A1 : A2);
            const __half* cW = (NPASS == 1 || lp == 0) ? W0 : (lp == 1 ? W1 : W2);
            const uint32_t bo = (uint32_t)st * GSS;
            cpa16(dA + bo,          cA + aoff + lk);
            cpa16(dA + bo + 4096u,  cA + aoff + (long long)32 * K + lk);
#pragma unroll
            for (int i = 0; i < 4; i++)
                cpa16(dW + bo + 4096u * i, cW + woff + (long long)32 * K * i + lk);
            lk += 64; if (lk == K) { lk = 0; lp++; }
        }
        asm volatile("cp.async.commit_group;" ::: "memory");
    }

    for (int kt = 0; kt < TT; kt++) {
        asm volatile("cp.async.wait_group 2;" ::: "memory");
        __syncthreads();
        const uint32_t buf = sb + (uint32_t)(kt & 3) * GSS;

#pragma unroll
        for (int s = 0; s < 4; s++) {
            const uint32_t cb = (uint32_t)s * 32;
            uint32_t ah[2][4], bh[2][4];
#pragma unroll
            for (int t = 0; t < 2; t++) {
                ldm4(ah[t], buf + aOff[t] + ((cb + lcol) ^ aXor[t]));
                ldm4(bh[t], buf + bOff[t] + ((cb + lcol) ^ bXor[t]));
            }
#pragma unroll
            for (int mt = 0; mt < 2; mt++)
#pragma unroll
                for (int n8 = 0; n8 < 4; n8++) {
                    uint32_t bf[2] = { bh[n8 >> 1][n8 & 1], bh[n8 >> 1][(n8 & 1) + 2] };
                    mma16816(acc[mt][n8], ah[mt], bf);
                }
        }

        if (kt + 3 < TT) {
            const __half* cA = (NPASS == 1 || lp == 0) ? A0 : (lp == 1 ? A1 : A2);
            const __half* cW = (NPASS == 1 || lp == 0) ? W0 : (lp == 1 ? W1 : W2);
            const uint32_t bo = (uint32_t)((kt + 3) & 3) * GSS;
            cpa16(dA + bo,          cA + aoff + lk);
            cpa16(dA + bo + 4096u,  cA + aoff + (long long)32 * K + lk);
#pragma unroll
            for (int i = 0; i < 4; i++)
                cpa16(dW + bo + 4096u * i, cW + woff + (long long)32 * K * i + lk);
            lk += 64; if (lk == K) { lk = 0; lp++; }
        }
        asm volatile("cp.async.commit_group;" ::: "memory");
    }

    const int er = lane >> 2;
    const int ec = (lane & 3) * 2;
#pragma unroll
    for (int mt = 0; mt < 2; mt++) {
        const int row = m0 + wm + mt * 16 + er;
#pragma unroll
        for (int n8 = 0; n8 < 4; n8++) {
            const int col = n0 + wn + n8 * 8 + ec;
            long long off = (long long)row * N + col;
            epi2<EPI>(C, OH, OL, off,                    acc[mt][n8][0], acc[mt][n8][1]);
            epi2<EPI>(C, OH, OL, off + (long long)8 * N, acc[mt][n8][2], acc[mt][n8][3]);
        }
    }
}

// ---------------- embedding gather ----------------
__global__ void embed_kernel(const int* __restrict__ idx,
                             const float* __restrict__ emb,
                             float* __restrict__ x)
{
    int row = blockIdx.x;
    int id  = idx[row];
    int t   = threadIdx.x;
    float4 v = *(const float4*)&emb[(long long)id * DIM + t * 4];
    *(float4*)&x[(long long)row * DIM + t * 4] = v;
}

// ---------------- rmsnorm -> fp16 (hi only) ----------------
__global__ void rmsnorm_h_kernel(const float* __restrict__ x,
                                 const float* __restrict__ w,
                                 __half* __restrict__ OH)
{
    __shared__ float red[8];
    int row = blockIdx.x;
    int t   = threadIdx.x;
    const float4* xr = (const float4*)(x + (long long)row * DIM);
    float4 v = xr[t];
    float ss = v.x * v.x + v.y * v.y + v.z * v.z + v.w * v.w;
#pragma unroll
    for (int o = 16; o > 0; o >>= 1) ss += __shfl_xor_sync(0xffffffffu, ss, o);
    if ((t & 31) == 0) red[t >> 5] = ss;
    __syncthreads();
    float tot = red[0] + red[1] + red[2] + red[3] + red[4] + red[5] + red[6] + red[7];
    float r = rsqrtf(tot * (1.f / (float)DIM) + 1e-6f);
    float4 wv = ((const float4*)w)[t];
    ((uint2*)(OH + (long long)row * DIM))[t] =
        make_uint2(pkh2(v.x * r * wv.x, v.y * r * wv.y),
                   pkh2(v.z * r * wv.z, v.w * r * wv.w));
}

// ======== flash attention on tensor cores (HD=64, fp16 hi/lo, 3-pass MMA) ========
// Inputs are PRE-SPLIT fp16 hi/lo (qkv written by the QKV GEMM epilogue).
// Output: fp16 hi only (o-proj is 2-pass on weights now).
#define FQH 0
#define FQL 8192
#define FKH 16384
#define FKL 24576
#define FVH 32768
#define FVL 40960
__device__ __forceinline__ uint32_t fsw(int row, int cbyte) {
    return (uint32_t)(row * 128 + (cbyte ^ ((row & 7) << 4)));
}
__global__ void __launch_bounds__(128) flash_mma(const __half* __restrict__ qh,
                                                 const __half* __restrict__ ql,
                                                 __half* __restrict__ OH)
{
    __shared__ char sm[49152];
    const uint32_t sb = smem_u32(sm);
    const int qb  = blockIdx.x * 64;
    const int hh  = blockIdx.y;
    const int b   = blockIdx.z;
    const int tid = threadIdx.x;
    const int lane = tid & 31;
    const int wq  = tid >> 5;
    const long long base = (long long)b * SEQT * T3D + hh * 64;

#pragma unroll
    for (int u = 0; u < 4; u++) {
        int slot = u * 128 + tid;
        int r = slot >> 3, c = slot & 7;
        long long go = base + (long long)(qb + r) * T3D + c * 8;
        uint32_t dst = sb + FQH + fsw(r, c * 16);
        cpa16(dst, qh + go);
        cpa16(dst + (FQL - FQH), ql + go);
    }

    const int g   = lane >> 2;
    const int tg  = lane & 3;
    const int lrow = ((lane >> 3) & 1) * 8 + (lane & 7);
    const uint32_t lcol = ((uint32_t)lane >> 4) * 16;

    float o[8][4];
#pragma unroll
    for (int j = 0; j < 8; j++)
#pragma unroll
        for (int e = 0; e < 4; e++) o[j][e] = 0.f;
    float m0 = -1e30f, m1 = -1e30f, l0 = 0.f, l1 = 0.f;

    for (int k0 = 0; k0 <= qb; k0 += 64) {
        __syncthreads();
#pragma unroll
        for (int u = 0; u < 4; u++) {
            int slot = u * 128 + tid;
            int r = slot >> 3, c = slot & 7;
            long long go = base + (long long)(k0 + r) * T3D + DIM + c * 8;
            uint32_t sw = fsw(r, c * 16);
            uint32_t dk = sb + FKH + sw;
            cpa16(dk, qh + go);
            cpa16(dk + (FKL - FKH), ql + go);
            uint32_t dv = sb + FVH + sw;
            cpa16(dv, qh + go + DIM);
            cpa16(dv + (FVL - FVH), ql + go + DIM);
        }
        asm volatile("cp.async.wait_all;" ::: "memory");
        __syncthreads();

        float s[8][4];
#pragma unroll
        for (int j = 0; j < 8; j++)
#pragma unroll
            for (int e = 0; e < 4; e++) s[j][e] = 0.f;
#pragma unroll
        for (int sl = 0; sl < 4; sl++) {
            const uint32_t cb = (uint32_t)sl * 32;
            uint32_t qfh[4], qfl[4];
            {
                int ra = wq * 16 + lrow;
                uint32_t adr = sb + FQH + (uint32_t)ra * 128u + ((cb + lcol) ^ ((uint32_t)(ra & 7) << 4));
                ldm4(qfh, adr);
                ldm4(qfl, adr + (FQL - FQH));
            }
#pragma unroll
            for (int t = 0; t < 4; t++) {
                int rb = t * 16 + lrow;
                uint32_t adr = sb + FKH + (uint32_t)rb * 128u + ((cb + lcol) ^ ((uint32_t)(rb & 7) << 4));
                uint32_t kh[4], kl[4];
                ldm4(kh, adr);
                ldm4(kl, adr + (FKL - FKH));
#pragma unroll
                for (int e = 0; e < 2; e++) {
                    uint32_t bh[2] = { kh[e], kh[e + 2] };
                    uint32_t bl[2] = { kl[e], kl[e + 2] };
                    mma16816(s[2 * t + e], qfh, bh);
                    mma16816(s[2 * t + e], qfh, bl);
                    mma16816(s[2 * t + e], qfl, bh);
                }
            }
        }
#pragma unroll
        for (int j = 0; j < 8; j++)
#pragma unroll
            for (int e = 0; e < 4; e++) s[j][e] *= 0.125f;

        if (k0 + 64 > qb) {
            const int q0 = qb + wq * 16 + g;
#pragma unroll
            for (int j = 0; j < 8; j++) {
                int key = k0 + 8 * j + 2 * tg;
                if (key     > q0)     s[j][0] = -1e30f;
                if (key + 1 > q0)     s[j][1] = -1e30f;
                if (key     > q0 + 8) s[j][2] = -1e30f;
                if (key + 1 > q0 + 8) s[j][3] = -1e30f;
            }
        }

        float mx0 = -1e30f, mx1 = -1e30f;
#pragma unroll
        for (int j = 0; j < 8; j++) {
            mx0 = fmaxf(mx0, fmaxf(s[j][0], s[j][1]));
            mx1 = fmaxf(mx1, fmaxf(s[j][2], s[j][3]));
        }
        mx0 = fmaxf(mx0, __shfl_xor_sync(0xffffffffu, mx0, 1));
        mx0 = fmaxf(mx0, __shfl_xor_sync(0xffffffffu, mx0, 2));
        mx1 = fmaxf(mx1, __shfl_xor_sync(0xffffffffu, mx1, 1));
        mx1 = fmaxf(mx1, __shfl_xor_sync(0xffffffffu, mx1, 2));
        const float mn0 = fmaxf(m0, mx0), mn1 = fmaxf(m1, mx1);
        const float c0 = __expf(m0 - mn0), c1 = __expf(m1 - mn1);
        float ls0 = 0.f, ls1 = 0.f;
        uint32_t ph[8][2], pl[8][2];
#pragma unroll
        for (int j = 0; j < 8; j++) {
            float p0 = __expf(s[j][0] - mn0);
            float p1 = __expf(s[j][1] - mn0);
            float p2 = __expf(s[j][2] - mn1);
            float p3 = __expf(s[j][3] - mn1);
            ls0 += p0 + p1; ls1 += p2 + p3;
            split2h(p0, p1, ph[j][0], pl[j][0]);
            split2h(p2, p3, ph[j][1], pl[j][1]);
        }
        ls0 += __shfl_xor_sync(0xffffffffu, ls0, 1);
        ls0 += __shfl_xor_sync(0xffffffffu, ls0, 2);
        ls1 += __shfl_xor_sync(0xffffffffu, ls1, 1);
        ls1 += __shfl_xor_sync(0xffffffffu, ls1, 2);
        l0 = l0 * c0 + ls0; l1 = l1 * c1 + ls1;
        m0 = mn0; m1 = mn1;
#pragma unroll
        for (int j = 0; j < 8; j++) {
            o[j][0] *= c0; o[j][1] *= c0;
            o[j][2] *= c1; o[j][3] *= c1;
        }

#pragma unroll
        for (int sl = 0; sl < 4; sl++) {
            uint32_t ah[4] = { ph[2 * sl][0], ph[2 * sl][1], ph[2 * sl + 1][0], ph[2 * sl + 1][1] };
            uint32_t al[4] = { pl[2 * sl][0], pl[2 * sl][1], pl[2 * sl + 1][0], pl[2 * sl + 1][1] };
#pragma unroll
            for (int t = 0; t < 4; t++) {
                int rv = sl * 16 + lrow;
                uint32_t adr = sb + FVH + (uint32_t)rv * 128u +
                               (((uint32_t)t * 32 + lcol) ^ ((uint32_t)(rv & 7) << 4));
                uint32_t vh[4], vl[4];
                ldm4t(vh, adr);
                ldm4t(vl, adr + (FVL - FVH));
#pragma unroll
                for (int e = 0; e < 2; e++) {
                    uint32_t bh[2] = { vh[2 * e], vh[2 * e + 1] };
                    uint32_t bl[2] = { vl[2 * e], vl[2 * e + 1] };
                    mma16816(o[2 * t + e], ah, bh);
                    mma16816(o[2 * t + e], ah, bl);
                    mma16816(o[2 * t + e], al, bh);
                }
            }
        }
    }

    const float i0 = 1.f / l0, i1 = 1.f / l1;
    const int row0 = qb + wq * 16 + g;
#pragma unroll
    for (int j = 0; j < 8; j++) {
        const int col = hh * 64 + 8 * j + 2 * tg;
        long long off0 = ((long long)b * SEQT + row0) * DIM + col;
        long long off1 = off0 + (long long)8 * DIM;
        *(uint32_t*)(OH + off0) = pkh2(o[j][0] * i0, o[j][1] * i0);
        *(uint32_t*)(OH + off1) = pkh2(o[j][2] * i1, o[j][3] * i1);
    }
}

// ---------------- launch ----------------
#define GEMM_SMEM (4 * 24576 + 1024)

static inline void conv_launch(const float* s, __half* H, long long n) {
    conv_kernel<<<(unsigned)((n / 4 + 255) / 256), 256>>>(s, H, n);
}
static inline void wsplit_launch(const float* s, __half* H, __half* L, long long n) {
    wsplit_kernel<<<(unsigned)((n / 4 + 255) / 256), 256>>>(s, H, L, n);
}

extern "C" void kernel_launch(void* const* d_in, const int* in_sizes, int n_in,
                              void* d_out, int out_size)
{
    (void)in_sizes; (void)n_in; (void)out_size;
    const int*   idx  = (const int*)d_in[0];
    const float* emb  = (const float*)d_in[1];
    const float* ln1  = (const float*)d_in[2];
    const float* qkvw = (const float*)d_in[3];
    const float* ow   = (const float*)d_in[4];
    const float* ln2  = (const float*)d_in[5];
    const float* gw   = (const float*)d_in[6];
    const float* uw   = (const float*)d_in[7];
    const float* dw   = (const float*)d_in[8];
    const float* lnf  = (const float*)d_in[9];

    float *x, *gate;
    __half *q3h, *q3l, *hh, *a2h;
    __half *qkvh, *owh, *owl, *gwh, *uwh, *dwh, *dwl, *embh;
    cudaGetSymbolAddress((void**)&x,    g_x);
    cudaGetSymbolAddress((void**)&gate, g_gate);
    cudaGetSymbolAddress((void**)&q3h,  g_q3h);
    cudaGetSymbolAddress((void**)&q3l,  g_q3l);
    cudaGetSymbolAddress((void**)&hh,   g_hh);
    cudaGetSymbolAddress((void**)&a2h,  g_2h);
    cudaGetSymbolAddress((void**)&qkvh, g_qkvh);
    cudaGetSymbolAddress((void**)&owh,  g_owh);
    cudaGetSymbolAddress((void**)&owl,  g_owl);
    cudaGetSymbolAddress((void**)&gwh,  g_gwh);
    cudaGetSymbolAddress((void**)&uwh,  g_uwh);
    cudaGetSymbolAddress((void**)&dwh,  g_dwh);
    cudaGetSymbolAddress((void**)&dwl,  g_dwl);
    cudaGetSymbolAddress((void**)&embh, g_embh);

    cudaFuncSetAttribute(gemm_p<1,0>, cudaFuncAttributeMaxDynamicSharedMemorySize, GEMM_SMEM);
    cudaFuncSetAttribute(gemm_p<1,2>, cudaFuncAttributeMaxDynamicSharedMemorySize, GEMM_SMEM);
    cudaFuncSetAttribute(gemm_p<1,3>, cudaFuncAttributeMaxDynamicSharedMemorySize, GEMM_SMEM);
    cudaFuncSetAttribute(gemm_p<2,1>, cudaFuncAttributeMaxDynamicSharedMemorySize, GEMM_SMEM);

    conv_launch(qkvw, qkvh, QKV_WN);                           // 0
    embed_kernel<<<BT, 256>>>(idx, emb, x);                    // 1

    for (int l = 0; l < NL; l++) {
        const __half* qw = qkvh + (long long)l * T3D * DIM;
        const __half* oh = owh + (long long)l * DIM * DIM;
        const __half* ol = owl + (long long)l * DIM * DIM;
        const __half* gh = gwh + (long long)l * DIFF * DIM;
        const __half* uh = uwh + (long long)l * DIFF * DIM;
        const __half* dh = dwh + (long long)l * DIM * DIFF;
        const __half* dl = dwl + (long long)l * DIM * DIFF;

        rmsnorm_h_kernel<<<BT, 256>>>(x, ln1 + (long long)l * DIM, hh);          // 2
        gemm_p<1,3><<<dim3(T3D / 128, BT / 64), 256, GEMM_SMEM>>>(               // 3 <- profiled
            hh, nullptr, nullptr, qw, nullptr, nullptr,
            nullptr, q3h, q3l, T3D, DIM);
        if (l == 0) {
            conv_launch(gw, gwh, G_WN);
            conv_launch(uw, uwh, G_WN);
            conv_launch(emb, embh, E_WN);
            wsplit_launch(ow, owh, owl, O_WN);
            wsplit_launch(dw, dwh, dwl, D_WN);
        }
        flash_mma<<<dim3(SEQT / 64, 16, 2), 128>>>(q3h, q3l, hh);
        // o-proj: 2-pass (act hi only) -> hh*(owh + owl)
        gemm_p<2,1><<<dim3(DIM / 128, BT / 64), 256, GEMM_SMEM>>>(
            hh, hh, nullptr, oh, ol, nullptr,
            x, nullptr, nullptr, DIM, DIM);
        rmsnorm_h_kernel<<<BT, 256>>>(x, ln2 + (long long)l * DIM, hh);
        gemm_p<1,0><<<dim3(DIFF / 128, BT / 64), 256, GEMM_SMEM>>>(
            hh, nullptr, nullptr, gh, nullptr, nullptr,
            gate, nullptr, nullptr, DIFF, DIM);
        gemm_p<1,2><<<dim3(DIFF / 128, BT / 64), 256, GEMM_SMEM>>>(
            hh, nullptr, nullptr, uh, nullptr, nullptr,
            gate, a2h, nullptr, DIFF, DIM);
        // down-proj: 2-pass (act hi only) -> a2h*(dwh + dwl)
        gemm_p<2,1><<<dim3(DIM / 128, BT / 64), 256, GEMM_SMEM>>>(
            a2h, a2h, nullptr, dh, dl, nullptr,
            x, nullptr, nullptr, DIM, DIFF);
    }

    rmsnorm_h_kernel<<<BT, 256>>>(x, lnf, hh);
    gemm_p<1,0><<<dim3(NVOC / 128, BT / 64), 256, GEMM_SMEM>>>(
        hh, nullptr, nullptr, embh, nullptr, nullptr,
        (float*)d_out, nullptr, nullptr, NVOC, DIM);
}

// round 17
// speedup vs baseline: 1.1909x; 1.0164x over previous
#include <cuda_runtime.h>
#include <cuda_fp16.h>
#include <stdint.h>

// ---------------- problem constants ----------------
#define BT    4096        // B*T
#define SEQT  2048        // T
#define DIM   1024        // D
#define T3D   3072        // 3*D
#define DIFF  2048        // DI
#define NL    8           // layers
#define NVOC  32000       // vocab

#define QKV_WN ((long long)NL * T3D * DIM)
#define O_WN   ((long long)NL * DIM * DIM)
#define G_WN   ((long long)NL * DIFF * DIM)
#define D_WN   ((long long)NL * DIM * DIFF)
#define E_WN   ((long long)NVOC * DIM)

// ---------------- scratch ----------------
__device__ float g_x[BT * DIM];               // residual (fp32)
__device__ __half g_q3h[BT * T3D], g_q3l[BT * T3D]; // qkv hi/lo (fp16)
__device__ __half g_hh[BT * DIM];             // activations (fp16, hi only)
__device__ __half g_2h[BT * DIFF];            // mlp mid (fp16, hi only)
// fp16 weights: hi for all; lo only where multi-pass (o, down)
__device__ __half g_qkvh[QKV_WN];
__device__ __half g_owh[O_WN],  g_owl[O_WN];
__device__ __half g_gwh[G_WN];
__device__ __half g_uwh[G_WN];
__device__ __half g_dwh[D_WN],  g_dwl[D_WN];
__device__ __half g_embh[E_WN];

// ---------------- helpers ----------------
__device__ __forceinline__ uint32_t smem_u32(const void* p) {
    uint32_t a;
    asm("{ .reg .u64 t; cvta.to.shared.u64 t, %1; cvt.u32.u64 %0, t; }" : "=r"(a) : "l"(p));
    return a;
}
__device__ __forceinline__ void ldm4(uint32_t* r, uint32_t a) {
    asm volatile("ldmatrix.sync.aligned.m8n8.x4.shared.b16 {%0,%1,%2,%3}, [%4];"
                 : "=r"(r[0]), "=r"(r[1]), "=r"(r[2]), "=r"(r[3]) : "r"(a));
}
__device__ __forceinline__ void ldm4t(uint32_t* r, uint32_t a) {
    asm volatile("ldmatrix.sync.aligned.m8n8.x4.trans.shared.b16 {%0,%1,%2,%3}, [%4];"
                 : "=r"(r[0]), "=r"(r[1]), "=r"(r[2]), "=r"(r[3]) : "r"(a));
}
__device__ __forceinline__ void mma16816(float* d, const uint32_t* a, const uint32_t* b) {
    asm volatile(
        "mma.sync.aligned.m16n8k16.row.col.f32.f16.f16.f32 "
        "{%0,%1,%2,%3}, {%4,%5,%6,%7}, {%8,%9}, {%0,%1,%2,%3};"
        : "+f"(d[0]), "+f"(d[1]), "+f"(d[2]), "+f"(d[3])
        : "r"(a[0]), "r"(a[1]), "r"(a[2]), "r"(a[3]), "r"(b[0]), "r"(b[1]));
}
__device__ __forceinline__ void cpa16(uint32_t d, const void* s) {
    asm volatile("cp.async.cg.shared.global [%0], [%1], 16;" :: "r"(d), "l"(s));
}
__device__ __forceinline__ uint32_t pkh2(float x, float y) {
    __half2 h = __floats2half2_rn(x, y);
    return *reinterpret_cast<uint32_t*>(&h);
}
__device__ __forceinline__ void split2h(float x, float y, uint32_t& h, uint32_t& l) {
    __half2 hb = __floats2half2_rn(x, y);
    h = *reinterpret_cast<uint32_t*>(&hb);
    l = pkh2(x - __half2float(__low2half(hb)), y - __half2float(__high2half(hb)));
}
__device__ __forceinline__ float silu_f(float x) { return x / (1.f + __expf(-x)); }

// ---------------- weight convert: fp32 -> fp16 (hi only) ----------------
__global__ void conv_kernel(const float* __restrict__ s,
                            __half* __restrict__ H, long long n)
{
    long long i = ((long long)blockIdx.x * 256 + threadIdx.x) * 4;
    if (i >= n) return;
    float4 v = *(const float4*)(s + i);
    *(uint2*)(H + i) = make_uint2(pkh2(v.x, v.y), pkh2(v.z, v.w));
}

// ---------------- weight split: fp32 -> fp16 hi + lo ----------------
__global__ void wsplit_kernel(const float* __restrict__ s,
                              __half* __restrict__ H,
                              __half* __restrict__ L, long long n)
{
    long long i = ((long long)blockIdx.x * 256 + threadIdx.x) * 4;
    if (i >= n) return;
    float4 v = *(const float4*)(s + i);
    uint32_t h0, l0, h1, l1;
    split2h(v.x, v.y, h0, l0);
    split2h(v.z, v.w, h1, l1);
    *(uint2*)(H + i) = make_uint2(h0, h1);
    *(uint2*)(L + i) = make_uint2(l0, l1);
}

// EPI 0: C=acc ; 1: C+=acc ; 3: OH/OL = fp16 hi/lo split(acc)
template <int EPI>
__device__ __forceinline__ void epi2(float* __restrict__ C,
                                     __half* __restrict__ OH,
                                     __half* __restrict__ OL,
                                     long long off, float x, float y)
{
    if (EPI == 0) {
        *(float2*)(C + off) = make_float2(x, y);
    } else if (EPI == 1) {
        float2 c = *(const float2*)(C + off);
        *(float2*)(C + off) = make_float2(c.x + x, c.y + y);
    } else {
        uint32_t h, l;
        split2h(x, y, h, l);
        *(uint32_t*)(OH + off) = h;
        *(uint32_t*)(OL + off) = l;
    }
}

// ============ unified multi-pass fp16 mma.sync GEMM ============
// C[M,N] = sum over passes p of Ap[M,K] @ Wp[N,K]^T  (fp32 accumulate).
// CTA tile 64x128, BK=64, 256 threads = 8 warps (2 M x 4 N, warp 32x32).
// Stage 24KB (A 8KB @0, W 16KB @8K), 4 stages = 96KB -> 2 CTAs/SM.
#define GSS 24576u
template <int NPASS, int EPI>
__global__ void __launch_bounds__(256, 2) gemm_p(
    const __half* __restrict__ A0, const __half* __restrict__ A1,
    const __half* __restrict__ W0, const __half* __restrict__ W1,
    float* __restrict__ C, __half* __restrict__ OH, __half* __restrict__ OL,
    int N, int K)
{
    extern __shared__ char dsm_raw[];
    char* dsm = (char*)(((uintptr_t)dsm_raw + 1023) & ~(uintptr_t)1023);
    const uint32_t sb = smem_u32(dsm);

    const int tid = threadIdx.x;
    const int wid = tid >> 5;
    const int lane = tid & 31;
    const int m0 = blockIdx.y * 64;
    const int n0 = blockIdx.x * 128;

    const int prow = tid >> 3;
    const int pcc  = tid & 7;
    const long long aoff = (long long)(m0 + prow) * K + pcc * 8;
    const long long woff = (long long)(n0 + prow) * K + pcc * 8;
    const uint32_t pdst = (uint32_t)prow * 128u +
                          (((uint32_t)pcc * 16u) ^ ((uint32_t)(prow & 7) << 4));
    const uint32_t dA = sb + pdst;
    const uint32_t dW = sb + 8192u + pdst;

    const int wm = (wid >> 2) * 32;
    const int wn = (wid & 3) * 32;
    const int lrow = ((lane >> 3) & 1) * 8 + (lane & 7);
    const uint32_t lcol = ((uint32_t)lane >> 4) * 16;
    uint32_t aOff[2], aXor[2], bOff[2], bXor[2];
#pragma unroll
    for (int t = 0; t < 2; t++) {
        int ra = wm + t * 16 + lrow;
        aOff[t] = (uint32_t)ra * 128u; aXor[t] = (uint32_t)(ra & 7) << 4;
        int rb = wn + t * 16 + lrow;
        bOff[t] = 8192u + (uint32_t)rb * 128u; bXor[t] = (uint32_t)(rb & 7) << 4;
    }

    float acc[2][4][4];
#pragma unroll
    for (int i = 0; i < 2; i++)
#pragma unroll
        for (int j = 0; j < 4; j++)
#pragma unroll
            for (int k = 0; k < 4; k++) acc[i][j][k] = 0.f;

    const int NT = K >> 6;
    const int TT = NPASS * NT;
    int lp = 0, lk = 0;

#pragma unroll
    for (int st = 0; st < 3; st++) {
        if (st < TT) {
            const __half* cA = (NPASS == 1 || lp == 0) ? A0 : A1;
            const __half* cW = (NPASS == 1 || lp == 0) ? W0 : W1;
            const uint32_t bo = (uint32_t)st * GSS;
            cpa16(dA + bo,          cA + aoff + lk);
            cpa16(dA + bo + 4096u,  cA + aoff + (long long)32 * K + lk);
#pragma unroll
            for (int i = 0; i < 4; i++)
                cpa16(dW + bo + 4096u * i, cW + woff + (long long)32 * K * i + lk);
            lk += 64; if (lk == K) { lk = 0; lp++; }
        }
        asm volatile("cp.async.commit_group;" ::: "memory");
    }

    for (int kt = 0; kt < TT; kt++) {
        asm volatile("cp.async.wait_group 2;" ::: "memory");
        __syncthreads();
        const uint32_t buf = sb + (uint32_t)(kt & 3) * GSS;

#pragma unroll
        for (int s = 0; s < 4; s++) {
            const uint32_t cb = (uint32_t)s * 32;
            uint32_t ah[2][4], bh[2][4];
#pragma unroll
            for (int t = 0; t < 2; t++) {
                ldm4(ah[t], buf + aOff[t] + ((cb + lcol) ^ aXor[t]));
                ldm4(bh[t], buf + bOff[t] + ((cb + lcol) ^ bXor[t]));
            }
#pragma unroll
            for (int mt = 0; mt < 2; mt++)
#pragma unroll
                for (int n8 = 0; n8 < 4; n8++) {
                    uint32_t bf[2] = { bh[n8 >> 1][n8 & 1], bh[n8 >> 1][(n8 & 1) + 2] };
                    mma16816(acc[mt][n8], ah[mt], bf);
                }
        }

        if (kt + 3 < TT) {
            const __half* cA = (NPASS == 1 || lp == 0) ? A0 : A1;
            const __half* cW = (NPASS == 1 || lp == 0) ? W0 : W1;
            const uint32_t bo = (uint32_t)((kt + 3) & 3) * GSS;
            cpa16(dA + bo,          cA + aoff + lk);
            cpa16(dA + bo + 4096u,  cA + aoff + (long long)32 * K + lk);
#pragma unroll
            for (int i = 0; i < 4; i++)
                cpa16(dW + bo + 4096u * i, cW + woff + (long long)32 * K * i + lk);
            lk += 64; if (lk == K) { lk = 0; lp++; }
        }
        asm volatile("cp.async.commit_group;" ::: "memory");
    }

    const int er = lane >> 2;
    const int ec = (lane & 3) * 2;
#pragma unroll
    for (int mt = 0; mt < 2; mt++) {
        const int row = m0 + wm + mt * 16 + er;
#pragma unroll
        for (int n8 = 0; n8 < 4; n8++) {
            const int col = n0 + wn + n8 * 8 + ec;
            long long off = (long long)row * N + col;
            epi2<EPI>(C, OH, OL, off,                    acc[mt][n8][0], acc[mt][n8][1]);
            epi2<EPI>(C, OH, OL, off + (long long)8 * N, acc[mt][n8][2], acc[mt][n8][3]);
        }
    }
}

// ============ fused gate+up GEMM: OH = fp16(silu(A@Wg^T) * (A@Wu^T)) ============
// Same mainloop as gemm_p<2,_> but pass 0 accumulates gate, pass 1 up,
// into separate register accumulators. Numerically identical to the
// two-kernel version (fp32 gate accumulator never left registers).
__global__ void __launch_bounds__(256, 2) gemm_gu(
    const __half* __restrict__ A0,
    const __half* __restrict__ Wg, const __half* __restrict__ Wu,
    __half* __restrict__ OH, int N, int K)
{
    extern __shared__ char dsm_raw[];
    char* dsm = (char*)(((uintptr_t)dsm_raw + 1023) & ~(uintptr_t)1023);
    const uint32_t sb = smem_u32(dsm);

    const int tid = threadIdx.x;
    const int wid = tid >> 5;
    const int lane = tid & 31;
    const int m0 = blockIdx.y * 64;
    const int n0 = blockIdx.x * 128;

    const int prow = tid >> 3;
    const int pcc  = tid & 7;
    const long long aoff = (long long)(m0 + prow) * K + pcc * 8;
    const long long woff = (long long)(n0 + prow) * K + pcc * 8;
    const uint32_t pdst = (uint32_t)prow * 128u +
                          (((uint32_t)pcc * 16u) ^ ((uint32_t)(prow & 7) << 4));
    const uint32_t dA = sb + pdst;
    const uint32_t dW = sb + 8192u + pdst;

    const int wm = (wid >> 2) * 32;
    const int wn = (wid & 3) * 32;
    const int lrow = ((lane >> 3) & 1) * 8 + (lane & 7);
    const uint32_t lcol = ((uint32_t)lane >> 4) * 16;
    uint32_t aOff[2], aXor[2], bOff[2], bXor[2];
#pragma unroll
    for (int t = 0; t < 2; t++) {
        int ra = wm + t * 16 + lrow;
        aOff[t] = (uint32_t)ra * 128u; aXor[t] = (uint32_t)(ra & 7) << 4;
        int rb = wn + t * 16 + lrow;
        bOff[t] = 8192u + (uint32_t)rb * 128u; bXor[t] = (uint32_t)(rb & 7) << 4;
    }

    float accG[2][4][4], accU[2][4][4];
#pragma unroll
    for (int i = 0; i < 2; i++)
#pragma unroll
        for (int j = 0; j < 4; j++)
#pragma unroll
            for (int k = 0; k < 4; k++) { accG[i][j][k] = 0.f; accU[i][j][k] = 0.f; }

    const int NT = K >> 6;
    const int TT = 2 * NT;
    int lp = 0, lk = 0;

#pragma unroll
    for (int st = 0; st < 3; st++) {
        if (st < TT) {
            const __half* cW = (lp == 0) ? Wg : Wu;
            const uint32_t bo = (uint32_t)st * GSS;
            cpa16(dA + bo,          A0 + aoff + lk);
            cpa16(dA + bo + 4096u,  A0 + aoff + (long long)32 * K + lk);
#pragma unroll
            for (int i = 0; i < 4; i++)
                cpa16(dW + bo + 4096u * i, cW + woff + (long long)32 * K * i + lk);
            lk += 64; if (lk == K) { lk = 0; lp++; }
        }
        asm volatile("cp.async.commit_group;" ::: "memory");
    }

    for (int kt = 0; kt < TT; kt++) {
        asm volatile("cp.async.wait_group 2;" ::: "memory");
        __syncthreads();
        const uint32_t buf = sb + (uint32_t)(kt & 3) * GSS;
        const bool gpass = (kt < NT);

#pragma unroll
        for (int s = 0; s < 4; s++) {
            const uint32_t cb = (uint32_t)s * 32;
            uint32_t ah[2][4], bh[2][4];
#pragma unroll
            for (int t = 0; t < 2; t++) {
                ldm4(ah[t], buf + aOff[t] + ((cb + lcol) ^ aXor[t]));
                ldm4(bh[t], buf + bOff[t] + ((cb + lcol) ^ bXor[t]));
            }
            if (gpass) {
#pragma unroll
                for (int mt = 0; mt < 2; mt++)
#pragma unroll
                    for (int n8 = 0; n8 < 4; n8++) {
                        uint32_t bf[2] = { bh[n8 >> 1][n8 & 1], bh[n8 >> 1][(n8 & 1) + 2] };
                        mma16816(accG[mt][n8], ah[mt], bf);
                    }
            } else {
#pragma unroll
                for (int mt = 0; mt < 2; mt++)
#pragma unroll
                    for (int n8 = 0; n8 < 4; n8++) {
                        uint32_t bf[2] = { bh[n8 >> 1][n8 & 1], bh[n8 >> 1][(n8 & 1) + 2] };
                        mma16816(accU[mt][n8], ah[mt], bf);
                    }
            }
        }

        if (kt + 3 < TT) {
            const __half* cW = (lp == 0) ? Wg : Wu;
            const uint32_t bo = (uint32_t)((kt + 3) & 3) * GSS;
            cpa16(dA + bo,          A0 + aoff + lk);
            cpa16(dA + bo + 4096u,  A0 + aoff + (long long)32 * K + lk);
#pragma unroll
            for (int i = 0; i < 4; i++)
                cpa16(dW + bo + 4096u * i, cW + woff + (long long)32 * K * i + lk);
            lk += 64; if (lk == K) { lk = 0; lp++; }
        }
        asm volatile("cp.async.commit_group;" ::: "memory");
    }

    const int er = lane >> 2;
    const int ec = (lane & 3) * 2;
#pragma unroll
    for (int mt = 0; mt < 2; mt++) {
        const int row = m0 + wm + mt * 16 + er;
#pragma unroll
        for (int n8 = 0; n8 < 4; n8++) {
            const int col = n0 + wn + n8 * 8 + ec;
            long long off = (long long)row * N + col;
            *(uint32_t*)(OH + off) =
                pkh2(silu_f(accG[mt][n8][0]) * accU[mt][n8][0],
                     silu_f(accG[mt][n8][1]) * accU[mt][n8][1]);
            *(uint32_t*)(OH + off + (long long)8 * N) =
                pkh2(silu_f(accG[mt][n8][2]) * accU[mt][n8][2],
                     silu_f(accG[mt][n8][3]) * accU[mt][n8][3]);
        }
    }
}

// ---------------- embedding gather ----------------
__global__ void embed_kernel(const int* __restrict__ idx,
                             const float* __restrict__ emb,
                             float* __restrict__ x)
{
    int row = blockIdx.x;
    int id  = idx[row];
    int t   = threadIdx.x;
    float4 v = *(const float4*)&emb[(long long)id * DIM + t * 4];
    *(float4*)&x[(long long)row * DIM + t * 4] = v;
}

// ---------------- rmsnorm -> fp16 (hi only) ----------------
__global__ void rmsnorm_h_kernel(const float* __restrict__ x,
                                 const float* __restrict__ w,
                                 __half* __restrict__ OH)
{
    __shared__ float red[8];
    int row = blockIdx.x;
    int t   = threadIdx.x;
    const float4* xr = (const float4*)(x + (long long)row * DIM);
    float4 v = xr[t];
    float ss = v.x * v.x + v.y * v.y + v.z * v.z + v.w * v.w;
#pragma unroll
    for (int o = 16; o > 0; o >>= 1) ss += __shfl_xor_sync(0xffffffffu, ss, o);
    if ((t & 31) == 0) red[t >> 5] = ss;
    __syncthreads();
    float tot = red[0] + red[1] + red[2] + red[3] + red[4] + red[5] + red[6] + red[7];
    float r = rsqrtf(tot * (1.f / (float)DIM) + 1e-6f);
    float4 wv = ((const float4*)w)[t];
    ((uint2*)(OH + (long long)row * DIM))[t] =
        make_uint2(pkh2(v.x * r * wv.x, v.y * r * wv.y),
                   pkh2(v.z * r * wv.z, v.w * r * wv.w));
}

// ======== flash attention on tensor cores (HD=64, fp16 hi/lo, 3-pass MMA) ========
#define FQH 0
#define FQL 8192
#define FKH 16384
#define FKL 24576
#define FVH 32768
#define FVL 40960
__device__ __forceinline__ uint32_t fsw(int row, int cbyte) {
    return (uint32_t)(row * 128 + (cbyte ^ ((row & 7) << 4)));
}
__global__ void __launch_bounds__(128) flash_mma(const __half* __restrict__ qh,
                                                 const __half* __restrict__ ql,
                                                 __half* __restrict__ OH)
{
    __shared__ char sm[49152];
    const uint32_t sb = smem_u32(sm);
    const int qb  = blockIdx.x * 64;
    const int hh  = blockIdx.y;
    const int b   = blockIdx.z;
    const int tid = threadIdx.x;
    const int lane = tid & 31;
    const int wq  = tid >> 5;
    const long long base = (long long)b * SEQT * T3D + hh * 64;

#pragma unroll
    for (int u = 0; u < 4; u++) {
        int slot = u * 128 + tid;
        int r = slot >> 3, c = slot & 7;
        long long go = base + (long long)(qb + r) * T3D + c * 8;
        uint32_t dst = sb + FQH + fsw(r, c * 16);
        cpa16(dst, qh + go);
        cpa16(dst + (FQL - FQH), ql + go);
    }

    const int g   = lane >> 2;
    const int tg  = lane & 3;
    const int lrow = ((lane >> 3) & 1) * 8 + (lane & 7);
    const uint32_t lcol = ((uint32_t)lane >> 4) * 16;

    float o[8][4];
#pragma unroll
    for (int j = 0; j < 8; j++)
#pragma unroll
        for (int e = 0; e < 4; e++) o[j][e] = 0.f;
    float m0 = -1e30f, m1 = -1e30f, l0 = 0.f, l1 = 0.f;

    for (int k0 = 0; k0 <= qb; k0 += 64) {
        __syncthreads();
#pragma unroll
        for (int u = 0; u < 4; u++) {
            int slot = u * 128 + tid;
            int r = slot >> 3, c = slot & 7;
            long long go = base + (long long)(k0 + r) * T3D + DIM + c * 8;
            uint32_t sw = fsw(r, c * 16);
            uint32_t dk = sb + FKH + sw;
            cpa16(dk, qh + go);
            cpa16(dk + (FKL - FKH), ql + go);
            uint32_t dv = sb + FVH + sw;
            cpa16(dv, qh + go + DIM);
            cpa16(dv + (FVL - FVH), ql + go + DIM);
        }
        asm volatile("cp.async.wait_all;" ::: "memory");
        __syncthreads();

        float s[8][4];
#pragma unroll
        for (int j = 0; j < 8; j++)
#pragma unroll
            for (int e = 0; e < 4; e++) s[j][e] = 0.f;
#pragma unroll
        for (int sl = 0; sl < 4; sl++) {
            const uint32_t cb = (uint32_t)sl * 32;
            uint32_t qfh[4], qfl[4];
            {
                int ra = wq * 16 + lrow;
                uint32_t adr = sb + FQH + (uint32_t)ra * 128u + ((cb + lcol) ^ ((uint32_t)(ra & 7) << 4));
                ldm4(qfh, adr);
                ldm4(qfl, adr + (FQL - FQH));
            }
#pragma unroll
            for (int t = 0; t < 4; t++) {
                int rb = t * 16 + lrow;
                uint32_t adr = sb + FKH + (uint32_t)rb * 128u + ((cb + lcol) ^ ((uint32_t)(rb & 7) << 4));
                uint32_t kh[4], kl[4];
                ldm4(kh, adr);
                ldm4(kl, adr + (FKL - FKH));
#pragma unroll
                for (int e = 0; e < 2; e++) {
                    uint32_t bh[2] = { kh[e], kh[e + 2] };
                    uint32_t bl[2] = { kl[e], kl[e + 2] };
                    mma16816(s[2 * t + e], qfh, bh);
                    mma16816(s[2 * t + e], qfh, bl);
                    mma16816(s[2 * t + e], qfl, bh);
                }
            }
        }
#pragma unroll
        for (int j = 0; j < 8; j++)
#pragma unroll
            for (int e = 0; e < 4; e++) s[j][e] *= 0.125f;

        if (k0 + 64 > qb) {
            const int q0 = qb + wq * 16 + g;
#pragma unroll
            for (int j = 0; j < 8; j++) {
                int key = k0 + 8 * j + 2 * tg;
                if (key     > q0)     s[j][0] = -1e30f;
                if (key + 1 > q0)     s[j][1] = -1e30f;
                if (key     > q0 + 8) s[j][2] = -1e30f;
                if (key + 1 > q0 + 8) s[j][3] = -1e30f;
            }
        }

        float mx0 = -1e30f, mx1 = -1e30f;
#pragma unroll
        for (int j = 0; j < 8; j++) {
            mx0 = fmaxf(mx0, fmaxf(s[j][0], s[j][1]));
            mx1 = fmaxf(mx1, fmaxf(s[j][2], s[j][3]));
        }
        mx0 = fmaxf(mx0, __shfl_xor_sync(0xffffffffu, mx0, 1));
        mx0 = fmaxf(mx0, __shfl_xor_sync(0xffffffffu, mx0, 2));
        mx1 = fmaxf(mx1, __shfl_xor_sync(0xffffffffu, mx1, 1));
        mx1 = fmaxf(mx1, __shfl_xor_sync(0xffffffffu, mx1, 2));
        const float mn0 = fmaxf(m0, mx0), mn1 = fmaxf(m1, mx1);
        const float c0 = __expf(m0 - mn0), c1 = __expf(m1 - mn1);
        float ls0 = 0.f, ls1 = 0.f;
        uint32_t ph[8][2], pl[8][2];
#pragma unroll
        for (int j = 0; j < 8; j++) {
            float p0 = __expf(s[j][0] - mn0);
            float p1 = __expf(s[j][1] - mn0);
            float p2 = __expf(s[j][2] - mn1);
            float p3 = __expf(s[j][3] - mn1);
            ls0 += p0 + p1; ls1 += p2 + p3;
            split2h(p0, p1, ph[j][0], pl[j][0]);
            split2h(p2, p3, ph[j][1], pl[j][1]);
        }
        ls0 += __shfl_xor_sync(0xffffffffu, ls0, 1);
        ls0 += __shfl_xor_sync(0xffffffffu, ls0, 2);
        ls1 += __shfl_xor_sync(0xffffffffu, ls1, 1);
        ls1 += __shfl_xor_sync(0xffffffffu, ls1, 2);
        l0 = l0 * c0 + ls0; l1 = l1 * c1 + ls1;
        m0 = mn0; m1 = mn1;
#pragma unroll
        for (int j = 0; j < 8; j++) {
            o[j][0] *= c0; o[j][1] *= c0;
            o[j][2] *= c1; o[j][3] *= c1;
        }

#pragma unroll
        for (int sl = 0; sl < 4; sl++) {
            uint32_t ah[4] = { ph[2 * sl][0], ph[2 * sl][1], ph[2 * sl + 1][0], ph[2 * sl + 1][1] };
            uint32_t al[4] = { pl[2 * sl][0], pl[2 * sl][1], pl[2 * sl + 1][0], pl[2 * sl + 1][1] };
#pragma unroll
            for (int t = 0; t < 4; t++) {
                int rv = sl * 16 + lrow;
                uint32_t adr = sb + FVH + (uint32_t)rv * 128u +
                               (((uint32_t)t * 32 + lcol) ^ ((uint32_t)(rv & 7) << 4));
                uint32_t vh[4], vl[4];
                ldm4t(vh, adr);
                ldm4t(vl, adr + (FVL - FVH));
#pragma unroll
                for (int e = 0; e < 2; e++) {
                    uint32_t bh[2] = { vh[2 * e], vh[2 * e + 1] };
                    uint32_t bl[2] = { vl[2 * e], vl[2 * e + 1] };
                    mma16816(o[2 * t + e], ah, bh);
                    mma16816(o[2 * t + e], ah, bl);
                    mma16816(o[2 * t + e], al, bh);
                }
            }
        }
    }

    const float i0 = 1.f / l0, i1 = 1.f / l1;
    const int row0 = qb + wq * 16 + g;
#pragma unroll
    for (int j = 0; j < 8; j++) {
        const int col = hh * 64 + 8 * j + 2 * tg;
        long long off0 = ((long long)b * SEQT + row0) * DIM + col;
        long long off1 = off0 + (long long)8 * DIM;
        *(uint32_t*)(OH + off0) = pkh2(o[j][0] * i0, o[j][1] * i0);
        *(uint32_t*)(OH + off1) = pkh2(o[j][2] * i1, o[j][3] * i1);
    }
}

// ---------------- launch ----------------
#define GEMM_SMEM (4 * 24576 + 1024)

static inline void conv_launch(const float* s, __half* H, long long n) {
    conv_kernel<<<(unsigned)((n / 4 + 255) / 256), 256>>>(s, H, n);
}
static inline void wsplit_launch(const float* s, __half* H, __half* L, long long n) {
    wsplit_kernel<<<(unsigned)((n / 4 + 255) / 256), 256>>>(s, H, L, n);
}

extern "C" void kernel_launch(void* const* d_in, const int* in_sizes, int n_in,
                              void* d_out, int out_size)
{
    (void)in_sizes; (void)n_in; (void)out_size;
    const int*   idx  = (const int*)d_in[0];
    const float* emb  = (const float*)d_in[1];
    const float* ln1  = (const float*)d_in[2];
    const float* qkvw = (const float*)d_in[3];
    const float* ow   = (const float*)d_in[4];
    const float* ln2  = (const float*)d_in[5];
    const float* gw   = (const float*)d_in[6];
    const float* uw   = (const float*)d_in[7];
    const float* dw   = (const float*)d_in[8];
    const float* lnf  = (const float*)d_in[9];

    float *x;
    __half *q3h, *q3l, *hh, *a2h;
    __half *qkvh, *owh, *owl, *gwh, *uwh, *dwh, *dwl, *embh;
    cudaGetSymbolAddress((void**)&x,    g_x);
    cudaGetSymbolAddress((void**)&q3h,  g_q3h);
    cudaGetSymbolAddress((void**)&q3l,  g_q3l);
    cudaGetSymbolAddress((void**)&hh,   g_hh);
    cudaGetSymbolAddress((void**)&a2h,  g_2h);
    cudaGetSymbolAddress((void**)&qkvh, g_qkvh);
    cudaGetSymbolAddress((void**)&owh,  g_owh);
    cudaGetSymbolAddress((void**)&owl,  g_owl);
    cudaGetSymbolAddress((void**)&gwh,  g_gwh);
    cudaGetSymbolAddress((void**)&uwh,  g_uwh);
    cudaGetSymbolAddress((void**)&dwh,  g_dwh);
    cudaGetSymbolAddress((void**)&dwl,  g_dwl);
    cudaGetSymbolAddress((void**)&embh, g_embh);

    cudaFuncSetAttribute(gemm_p<1,0>, cudaFuncAttributeMaxDynamicSharedMemorySize, GEMM_SMEM);
    cudaFuncSetAttribute(gemm_p<1,3>, cudaFuncAttributeMaxDynamicSharedMemorySize, GEMM_SMEM);
    cudaFuncSetAttribute(gemm_p<2,1>, cudaFuncAttributeMaxDynamicSharedMemorySize, GEMM_SMEM);
    cudaFuncSetAttribute(gemm_gu, cudaFuncAttributeMaxDynamicSharedMemorySize, GEMM_SMEM);

    conv_launch(qkvw, qkvh, QKV_WN);                           // 0
    embed_kernel<<<BT, 256>>>(idx, emb, x);                    // 1

    for (int l = 0; l < NL; l++) {
        const __half* qw = qkvh + (long long)l * T3D * DIM;
        const __half* oh = owh + (long long)l * DIM * DIM;
        const __half* ol = owl + (long long)l * DIM * DIM;
        const __half* gh = gwh + (long long)l * DIFF * DIM;
        const __half* uh = uwh + (long long)l * DIFF * DIM;
        const __half* dh = dwh + (long long)l * DIM * DIFF;
        const __half* dl = dwl + (long long)l * DIM * DIFF;

        rmsnorm_h_kernel<<<BT, 256>>>(x, ln1 + (long long)l * DIM, hh);          // 2
        gemm_p<1,3><<<dim3(T3D / 128, BT / 64), 256, GEMM_SMEM>>>(               // 3 <- profiled
            hh, nullptr, qw, nullptr,
            nullptr, q3h, q3l, T3D, DIM);
        if (l == 0) {
            conv_launch(gw, gwh, G_WN);
            conv_launch(uw, uwh, G_WN);
            conv_launch(emb, embh, E_WN);
            wsplit_launch(ow, owh, owl, O_WN);
            wsplit_launch(dw, dwh, dwl, D_WN);
        }
        flash_mma<<<dim3(SEQT / 64, 16, 2), 128>>>(q3h, q3l, hh);
        // o-proj: 2-pass (act hi only) -> hh*(owh + owl)
        gemm_p<2,1><<<dim3(DIM / 128, BT / 64), 256, GEMM_SMEM>>>(
            hh, hh, oh, ol,
            x, nullptr, nullptr, DIM, DIM);
        rmsnorm_h_kernel<<<BT, 256>>>(x, ln2 + (long long)l * DIM, hh);
        // fused gate+up -> a2h = fp16(silu(hh@gw^T) * (hh@uw^T))
        gemm_gu<<<dim3(DIFF / 128, BT / 64), 256, GEMM_SMEM>>>(
            hh, gh, uh, a2h, DIFF, DIM);
        // down-proj: 2-pass (act hi only) -> a2h*(dwh + dwl)
        gemm_p<2,1><<<dim3(DIM / 128, BT / 64), 256, GEMM_SMEM>>>(
            a2h, a2h, dh, dl,
            x, nullptr, nullptr, DIM, DIFF);
    }

    rmsnorm_h_kernel<<<BT, 256>>>(x, lnf, hh);
    gemm_p<1,0><<<dim3(NVOC / 128, BT / 64), 256, GEMM_SMEM>>>(
        hh, nullptr, embh, nullptr,
        (float*)d_out, nullptr, nullptr, NVOC, DIM);
}